// round 10
// baseline (speedup 1.0000x reference)
#include <cuda_runtime.h>
#include <cuda_fp16.h>
#include <cstdint>

#define NN 100000
#define EE 3200000
#define DD 128
#define EPS 1e-5f

#define RBM 64                               // rows per GEMM block
#define GEMM_BLOCKS ((NN + RBM - 1) / RBM)   // 1563

// smem layout for tf32 GEMM
#define SA_STRIDE 260                        // 256 + 4 pad
#define SB_STRIDE 136                        // 128 + 8 pad
#define SA_FLOATS (64 * SA_STRIDE)           // 16640
#define SB_FLOATS (256 * SB_STRIDE)          // 34816
#define GEMM_SMEM ((SA_FLOATS + SB_FLOATS) * 4)   // 205824 B

// Scratch (allocation-free rule: __device__ globals; zero-initialized at load,
// and re-zeroed at the tail of output_kernel each execution so the graph can
// replay deterministically).
__device__ __half g_hhalf[NN * DD];  // fp16 copy of h for the gather
__device__ float g_neigh[NN * DD];   // mean-aggregated neighbor features
__device__ float g_rst[NN * DD];     // post-relu activations
__device__ int   g_cnt[NN];          // degree histogram (must be 0 on entry)
__device__ int   g_off[NN + 1];      // CSR exclusive offsets (+ total)
__device__ int   g_rank[EE];         // per-edge rank within its dst bucket
__device__ int   g_sorted[EE];       // src sorted by dst
__device__ float g_colsum[DD];       // must be 0 on entry
__device__ float g_colsumsq[DD];     // must be 0 on entry
__device__ float g_coefA[DD];
__device__ float g_coefB[DD];

// ---------------------------------------------------------------------------
// K0: fused degree histogram (+rank capture) + fp16 conversion of h.
// The hist atomics are latency-bound; the streaming conversion rides in the
// idle issue/LSU slots.
// ---------------------------------------------------------------------------
__global__ void hist_convert_kernel(const int* __restrict__ dst,
                                    const float* __restrict__ h) {
    int i = blockIdx.x * blockDim.x + threadIdx.x;
    int stride = gridDim.x * blockDim.x;

    // fp16 conversion: float4 -> 4 halves (uint2)
    const float4* h4 = (const float4*)h;
    uint2* o = (uint2*)g_hhalf;
    const int nf4 = NN * DD / 4;
    for (int f = i; f < nf4; f += stride) {
        float4 v = h4[f];
        __half2 lo = __floats2half2_rn(v.x, v.y);
        __half2 hi = __floats2half2_rn(v.z, v.w);
        uint2 u;
        u.x = *(uint32_t*)&lo;
        u.y = *(uint32_t*)&hi;
        o[f] = u;
    }

    // histogram + rank (int4 edge loads)
    const int4* d4 = (const int4*)dst;
    int4* r4 = (int4*)g_rank;
    const int n4 = EE / 4;
    for (int e = i; e < n4; e += stride) {
        int4 d = __ldg(&d4[e]);
        int4 r;
        r.x = atomicAdd(&g_cnt[d.x], 1);
        r.y = atomicAdd(&g_cnt[d.y], 1);
        r.z = atomicAdd(&g_cnt[d.z], 1);
        r.w = atomicAdd(&g_cnt[d.w], 1);
        r4[e] = r;
    }
}

// ---------------------------------------------------------------------------
// K1: single-block exclusive scan of g_cnt -> g_off (with total at g_off[NN])
// ---------------------------------------------------------------------------
#define SCAN_T 1024
#define CHUNK  ((NN + SCAN_T - 1) / SCAN_T)   // 98
__global__ void __launch_bounds__(SCAN_T, 1)
scan_kernel() {
    __shared__ int ss[SCAN_T];
    int t = threadIdx.x;
    int beg = t * CHUNK;
    int end = min(beg + CHUNK, NN);
    int s = 0;
    for (int i = beg; i < end; i++) s += g_cnt[i];
    ss[t] = s;
    __syncthreads();
    for (int d = 1; d < SCAN_T; d <<= 1) {
        int v = (t >= d) ? ss[t - d] : 0;
        __syncthreads();
        ss[t] += v;
        __syncthreads();
    }
    int run = ss[t] - s;
    for (int i = beg; i < end; i++) {
        g_off[i] = run;
        run += g_cnt[i];
    }
    if (t == SCAN_T - 1) g_off[NN] = ss[t];
}

// ---------------------------------------------------------------------------
// K2: CSR fill — atomic-free counting sort using precomputed ranks.
// ---------------------------------------------------------------------------
__global__ void fill_kernel(const int* __restrict__ src,
                            const int* __restrict__ dst) {
    int i = blockIdx.x * blockDim.x + threadIdx.x;
    int stride = gridDim.x * blockDim.x;
    const int4* s4 = (const int4*)src;
    const int4* d4 = (const int4*)dst;
    const int4* r4 = (const int4*)g_rank;
    const int n4 = EE / 4;
    for (int e = i; e < n4; e += stride) {
        int4 d = __ldg(&d4[e]);
        int4 s = __ldg(&s4[e]);
        int4 r = __ldg(&r4[e]);
        g_sorted[__ldg(&g_off[d.x]) + r.x] = s.x;
        g_sorted[__ldg(&g_off[d.y]) + r.y] = s.y;
        g_sorted[__ldg(&g_off[d.z]) + r.z] = s.z;
        g_sorted[__ldg(&g_off[d.w]) + r.w] = s.w;
    }
}

// ---------------------------------------------------------------------------
// K3 (profiled slot): aggregation over fp16 h — warp per node, lane = 4
// halves (uint2), unroll 8 rows; fp32 accumulation.
// ---------------------------------------------------------------------------
__device__ __forceinline__ void h2acc(float4& a, uint2 u) {
    __half2 lo = *(__half2*)&u.x;
    __half2 hi = *(__half2*)&u.y;
    float2 f0 = __half22float2(lo);
    float2 f1 = __half22float2(hi);
    a.x += f0.x; a.y += f0.y; a.z += f1.x; a.w += f1.y;
}

__global__ void __launch_bounds__(256)
agg_kernel() {
    int lane = threadIdx.x & 31;
    int gw = blockIdx.x * 8 + (threadIdx.x >> 5);
    int nw = gridDim.x * 8;
    const uint2* h2 = (const uint2*)g_hhalf;   // 32 uint2 per row
    for (int row = gw; row < NN; row += nw) {
        int beg = __ldg(&g_off[row]);
        int deg = __ldg(&g_off[row + 1]) - beg;
        float4 a0 = make_float4(0.f, 0.f, 0.f, 0.f);
        float4 a1 = a0, a2 = a0, a3 = a0;
        int j = 0;
        for (; j + 8 <= deg; j += 8) {
            int s0 = __ldg(&g_sorted[beg + j]);
            int s1 = __ldg(&g_sorted[beg + j + 1]);
            int s2 = __ldg(&g_sorted[beg + j + 2]);
            int s3 = __ldg(&g_sorted[beg + j + 3]);
            int s4 = __ldg(&g_sorted[beg + j + 4]);
            int s5 = __ldg(&g_sorted[beg + j + 5]);
            int s6 = __ldg(&g_sorted[beg + j + 6]);
            int s7 = __ldg(&g_sorted[beg + j + 7]);
            uint2 v0 = __ldg(&h2[(size_t)s0 * 32 + lane]);
            uint2 v1 = __ldg(&h2[(size_t)s1 * 32 + lane]);
            uint2 v2 = __ldg(&h2[(size_t)s2 * 32 + lane]);
            uint2 v3 = __ldg(&h2[(size_t)s3 * 32 + lane]);
            uint2 v4 = __ldg(&h2[(size_t)s4 * 32 + lane]);
            uint2 v5 = __ldg(&h2[(size_t)s5 * 32 + lane]);
            uint2 v6 = __ldg(&h2[(size_t)s6 * 32 + lane]);
            uint2 v7 = __ldg(&h2[(size_t)s7 * 32 + lane]);
            h2acc(a0, v0); h2acc(a1, v1); h2acc(a2, v2); h2acc(a3, v3);
            h2acc(a0, v4); h2acc(a1, v5); h2acc(a2, v6); h2acc(a3, v7);
        }
        for (; j < deg; j++) {
            int s = __ldg(&g_sorted[beg + j]);
            h2acc(a0, __ldg(&h2[(size_t)s * 32 + lane]));
        }
        float inv = 1.0f / fmaxf((float)deg, 1.0f);
        float4 r;
        r.x = (a0.x + a1.x + a2.x + a3.x) * inv;
        r.y = (a0.y + a1.y + a2.y + a3.y) * inv;
        r.z = (a0.z + a1.z + a2.z + a3.z) * inv;
        r.w = (a0.w + a1.w + a2.w + a3.w) * inv;
        ((float4*)(g_neigh + (size_t)row * DD))[lane] = r;
    }
}

// ---------------------------------------------------------------------------
// K4: TF32 tensor-core dual GEMM (concat K=256):
//   rst = relu([h | neigh] @ [Ws; Wn] + b), fused BN column stats.
// ---------------------------------------------------------------------------
__device__ __forceinline__ uint32_t f2tf32(float v) {
    uint32_t x;
    asm("cvt.rna.tf32.f32 %0, %1;" : "=r"(x) : "f"(v));
    return x;
}

__global__ void __launch_bounds__(256, 1)
dual_gemm_tf32(const float* __restrict__ h,
               const float* __restrict__ Wself,
               const float* __restrict__ Wneigh,
               const float* __restrict__ bias) {
    extern __shared__ float sm[];
    float* sA = sm;              // 64 x SA_STRIDE
    float* sB = sm + SA_FLOATS;  // 256 x SB_STRIDE

    const int t    = threadIdx.x;
    const int lane = t & 31;
    const int wid  = t >> 5;
    const int gid  = lane >> 2;   // 0..7
    const int tig  = lane & 3;    // 0..3
    const int wm   = wid & 1;     // warp row 0..1
    const int wn   = wid >> 1;    // warp col 0..3
    const int row_base = blockIdx.x * RBM;

    // --- cooperative A load: 64 rows x 256 cols = [h | neigh], cvt tf32 ---
    for (int f = t; f < 64 * 64; f += 256) {       // 64 float4 per row
        int r  = f >> 6;
        int c4 = f & 63;
        int row = row_base + r;
        float4 v = make_float4(0.f, 0.f, 0.f, 0.f);
        if (row < NN) {
            if (c4 < 32) v = ((const float4*)(h + (size_t)row * DD))[c4];
            else         v = ((const float4*)(g_neigh + (size_t)row * DD))[c4 - 32];
        }
        float* p = &sA[r * SA_STRIDE + c4 * 4];
        p[0] = __uint_as_float(f2tf32(v.x));
        p[1] = __uint_as_float(f2tf32(v.y));
        p[2] = __uint_as_float(f2tf32(v.z));
        p[3] = __uint_as_float(f2tf32(v.w));
    }
    // --- cooperative B load: rows 0..127 = Ws, 128..255 = Wn ---
    for (int f = t; f < 256 * 32; f += 256) {      // 32 float4 per row
        int k  = f >> 5;
        int n4 = f & 31;
        const float4* W = (k < 128) ? (const float4*)Wself : (const float4*)Wneigh;
        float4 v = __ldg(&W[(k & 127) * 32 + n4]);
        float* p = &sB[k * SB_STRIDE + n4 * 4];
        p[0] = __uint_as_float(f2tf32(v.x));
        p[1] = __uint_as_float(f2tf32(v.y));
        p[2] = __uint_as_float(f2tf32(v.z));
        p[3] = __uint_as_float(f2tf32(v.w));
    }
    __syncthreads();

    float acc[2][4][4];
    #pragma unroll
    for (int mi = 0; mi < 2; mi++)
        #pragma unroll
        for (int ni = 0; ni < 4; ni++)
            #pragma unroll
            for (int c = 0; c < 4; c++) acc[mi][ni][c] = 0.f;

    for (int k = 0; k < 256; k += 8) {
        uint32_t a[2][4], b[4][2];
        #pragma unroll
        for (int mi = 0; mi < 2; mi++) {
            int r0 = wm * 32 + mi * 16 + gid;
            a[mi][0] = __float_as_uint(sA[r0 * SA_STRIDE + k + tig]);
            a[mi][1] = __float_as_uint(sA[(r0 + 8) * SA_STRIDE + k + tig]);
            a[mi][2] = __float_as_uint(sA[r0 * SA_STRIDE + k + tig + 4]);
            a[mi][3] = __float_as_uint(sA[(r0 + 8) * SA_STRIDE + k + tig + 4]);
        }
        #pragma unroll
        for (int ni = 0; ni < 4; ni++) {
            int n0 = wn * 32 + ni * 8 + gid;
            b[ni][0] = __float_as_uint(sB[(k + tig) * SB_STRIDE + n0]);
            b[ni][1] = __float_as_uint(sB[(k + tig + 4) * SB_STRIDE + n0]);
        }
        #pragma unroll
        for (int mi = 0; mi < 2; mi++)
            #pragma unroll
            for (int ni = 0; ni < 4; ni++) {
                asm volatile(
                    "mma.sync.aligned.m16n8k8.row.col.f32.tf32.tf32.f32 "
                    "{%0,%1,%2,%3}, {%4,%5,%6,%7}, {%8,%9}, {%0,%1,%2,%3};"
                    : "+f"(acc[mi][ni][0]), "+f"(acc[mi][ni][1]),
                      "+f"(acc[mi][ni][2]), "+f"(acc[mi][ni][3])
                    : "r"(a[mi][0]), "r"(a[mi][1]), "r"(a[mi][2]), "r"(a[mi][3]),
                      "r"(b[ni][0]), "r"(b[ni][1]));
            }
    }

    // --- epilogue: bias, relu, store, per-thread BN stats ---
    float2 bv[4];
    #pragma unroll
    for (int ni = 0; ni < 4; ni++) {
        int col = wn * 32 + ni * 8 + 2 * tig;
        bv[ni] = *(const float2*)&bias[col];
    }

    float lsum[4][2], lsq[4][2];
    #pragma unroll
    for (int ni = 0; ni < 4; ni++) {
        lsum[ni][0] = lsum[ni][1] = 0.f;
        lsq[ni][0] = lsq[ni][1] = 0.f;
    }

    #pragma unroll
    for (int mi = 0; mi < 2; mi++) {
        #pragma unroll
        for (int half = 0; half < 2; half++) {
            int row = row_base + wm * 32 + mi * 16 + half * 8 + gid;
            if (row < NN) {
                #pragma unroll
                for (int ni = 0; ni < 4; ni++) {
                    int col = wn * 32 + ni * 8 + 2 * tig;
                    float v0 = fmaxf(acc[mi][ni][half * 2]     + bv[ni].x, 0.f);
                    float v1 = fmaxf(acc[mi][ni][half * 2 + 1] + bv[ni].y, 0.f);
                    lsum[ni][0] += v0; lsq[ni][0] += v0 * v0;
                    lsum[ni][1] += v1; lsq[ni][1] += v1 * v1;
                    *(float2*)&g_rst[(size_t)row * DD + col] = make_float2(v0, v1);
                }
            }
        }
    }

    // warp-reduce stats over gid lanes, then global atomics
    #pragma unroll
    for (int ni = 0; ni < 4; ni++)
        #pragma unroll
        for (int s = 0; s < 2; s++) {
            #pragma unroll
            for (int off = 4; off <= 16; off <<= 1) {
                lsum[ni][s] += __shfl_xor_sync(0xffffffffu, lsum[ni][s], off);
                lsq[ni][s]  += __shfl_xor_sync(0xffffffffu, lsq[ni][s],  off);
            }
        }
    if (gid == 0) {
        #pragma unroll
        for (int ni = 0; ni < 4; ni++) {
            int col = wn * 32 + ni * 8 + 2 * tig;
            atomicAdd(&g_colsum[col],       lsum[ni][0]);
            atomicAdd(&g_colsum[col + 1],   lsum[ni][1]);
            atomicAdd(&g_colsumsq[col],     lsq[ni][0]);
            atomicAdd(&g_colsumsq[col + 1], lsq[ni][1]);
        }
    }
}

// ---------------------------------------------------------------------------
// K5: finalize BN coefficients
// ---------------------------------------------------------------------------
__global__ void finalize_kernel(const float* __restrict__ gamma,
                                const float* __restrict__ beta) {
    int c = threadIdx.x;
    const float invN = 1.0f / (float)NN;
    float mean = g_colsum[c] * invN;
    float var  = g_colsumsq[c] * invN - mean * mean;
    float a = gamma[c] * rsqrtf(var + EPS);
    g_coefA[c] = a;
    g_coefB[c] = beta[c] - mean * a;
}

// ---------------------------------------------------------------------------
// K6: out = h + rst * A[c] + B[c]; tail re-zeroes counters/stats so the next
// graph replay starts from the required zero state.
// ---------------------------------------------------------------------------
__global__ void output_kernel(const float* __restrict__ h,
                              float* __restrict__ out) {
    int i = blockIdx.x * blockDim.x + threadIdx.x;
    int stride = gridDim.x * blockDim.x;
    const int nf4 = NN * DD / 4;
    for (int f = i; f < nf4; f += stride) {
        int cg = f & 31;
        float4 a  = ((const float4*)g_coefA)[cg];
        float4 bb = ((const float4*)g_coefB)[cg];
        float4 hv = ((const float4*)h)[f];
        float4 rv = ((const float4*)g_rst)[f];
        float4 o;
        o.x = hv.x + rv.x * a.x + bb.x;
        o.y = hv.y + rv.y * a.y + bb.y;
        o.z = hv.z + rv.z * a.z + bb.z;
        o.w = hv.w + rv.w * a.w + bb.w;
        ((float4*)out)[f] = o;
    }
    // re-zero for next execution (finalize already consumed the stats)
    for (int f = i; f < NN; f += stride) g_cnt[f] = 0;
    if (i < DD) { g_colsum[i] = 0.f; g_colsumsq[i] = 0.f; }
}

// ---------------------------------------------------------------------------
extern "C" void kernel_launch(void* const* d_in, const int* in_sizes, int n_in,
                              void* d_out, int out_size) {
    const float* h      = (const float*)d_in[0];
    const int*   src    = (const int*)d_in[1];
    const int*   dst    = (const int*)d_in[2];
    const float* Wself  = (const float*)d_in[3];
    const float* Wneigh = (const float*)d_in[4];
    const float* bias   = (const float*)d_in[5];
    const float* gamma  = (const float*)d_in[6];
    const float* beta   = (const float*)d_in[7];
    float*       out    = (float*)d_out;

    hist_convert_kernel<<<2048, 256>>>(dst, h);   // launch 0
    scan_kernel<<<1, SCAN_T>>>();                 // launch 1
    fill_kernel<<<2048, 256>>>(src, dst);         // launch 2
    agg_kernel<<<2048, 256>>>();                  // launch 3  <- profiled slot

    cudaFuncSetAttribute(dual_gemm_tf32,
                         cudaFuncAttributeMaxDynamicSharedMemorySize,
                         GEMM_SMEM);
    dual_gemm_tf32<<<GEMM_BLOCKS, 256, GEMM_SMEM>>>(h, Wself, Wneigh, bias);

    finalize_kernel<<<1, DD>>>(gamma, beta);
    output_kernel<<<2048, 256>>>(h, out);
}

// round 11
// speedup vs baseline: 1.3573x; 1.3573x over previous
#include <cuda_runtime.h>
#include <cuda_fp16.h>
#include <cstdint>

#define NN 100000
#define EE 3200000
#define DD 128
#define EPS 1e-5f

#define RBM 64                               // rows per GEMM block
#define GEMM_BLOCKS ((NN + RBM - 1) / RBM)   // 1563

// fp16 GEMM smem: A [64][264] halves, B(transposed) [128][264] halves
#define AK 264
#define A_HALVES (64 * AK)                   // 16896
#define B_HALVES (128 * AK)                  // 33792
#define GEMM_SMEM ((A_HALVES + B_HALVES) * 2)  // 101376 B

// Scratch (allocation-free rule: __device__ globals; zero-initialized at load,
// re-zeroed at the tail of output_kernel each execution).
__device__ __half g_hhalf[NN * DD];  // fp16 copy of h
__device__ float g_neigh[NN * DD];   // mean-aggregated neighbor features
__device__ float g_rst[NN * DD];     // post-relu activations
__device__ int   g_cnt[NN];          // degree histogram (must be 0 on entry)
__device__ int   g_off[NN + 1];      // CSR exclusive offsets (+ total)
__device__ int   g_cursor[NN];       // fill cursors
__device__ int   g_sorted[EE];       // src sorted by dst
__device__ float g_colsum[DD];       // must be 0 on entry
__device__ float g_colsumsq[DD];     // must be 0 on entry
__device__ float g_coefA[DD];
__device__ float g_coefB[DD];

// ---------------------------------------------------------------------------
// K0: fused degree histogram (RED, fire-and-forget) + fp16 conversion of h.
// ---------------------------------------------------------------------------
__global__ void hist_convert_kernel(const int* __restrict__ dst,
                                    const float* __restrict__ h) {
    int i = blockIdx.x * blockDim.x + threadIdx.x;
    int stride = gridDim.x * blockDim.x;

    const float4* h4 = (const float4*)h;
    uint2* o = (uint2*)g_hhalf;
    const int nf4 = NN * DD / 4;
    for (int f = i; f < nf4; f += stride) {
        float4 v = h4[f];
        __half2 lo = __floats2half2_rn(v.x, v.y);
        __half2 hi = __floats2half2_rn(v.z, v.w);
        uint2 u;
        u.x = *(uint32_t*)&lo;
        u.y = *(uint32_t*)&hi;
        o[f] = u;
    }

    const int4* d4 = (const int4*)dst;
    const int n4 = EE / 4;
    for (int e = i; e < n4; e += stride) {
        int4 d = __ldg(&d4[e]);
        atomicAdd(&g_cnt[d.x], 1);   // return unused -> RED
        atomicAdd(&g_cnt[d.y], 1);
        atomicAdd(&g_cnt[d.z], 1);
        atomicAdd(&g_cnt[d.w], 1);
    }
}

// ---------------------------------------------------------------------------
// K1: single-block exclusive scan of g_cnt -> g_off / g_cursor
// ---------------------------------------------------------------------------
#define SCAN_T 1024
#define CHUNK  ((NN + SCAN_T - 1) / SCAN_T)   // 98
__global__ void __launch_bounds__(SCAN_T, 1)
scan_kernel() {
    __shared__ int ss[SCAN_T];
    int t = threadIdx.x;
    int beg = t * CHUNK;
    int end = min(beg + CHUNK, NN);
    int s = 0;
    for (int i = beg; i < end; i++) s += g_cnt[i];
    ss[t] = s;
    __syncthreads();
    for (int d = 1; d < SCAN_T; d <<= 1) {
        int v = (t >= d) ? ss[t - d] : 0;
        __syncthreads();
        ss[t] += v;
        __syncthreads();
    }
    int run = ss[t] - s;
    for (int i = beg; i < end; i++) {
        g_off[i] = run;
        g_cursor[i] = run;
        run += g_cnt[i];
    }
    if (t == SCAN_T - 1) g_off[NN] = ss[t];
}

// ---------------------------------------------------------------------------
// K2: CSR fill — counting sort of src by dst (atomic cursors)
// ---------------------------------------------------------------------------
__global__ void fill_kernel(const int* __restrict__ src,
                            const int* __restrict__ dst) {
    int i = blockIdx.x * blockDim.x + threadIdx.x;
    int stride = gridDim.x * blockDim.x;
    const int4* s4 = (const int4*)src;
    const int4* d4 = (const int4*)dst;
    const int n4 = EE / 4;
    for (int e = i; e < n4; e += stride) {
        int4 d = __ldg(&d4[e]);
        int4 s = __ldg(&s4[e]);
        g_sorted[atomicAdd(&g_cursor[d.x], 1)] = s.x;
        g_sorted[atomicAdd(&g_cursor[d.y], 1)] = s.y;
        g_sorted[atomicAdd(&g_cursor[d.z], 1)] = s.z;
        g_sorted[atomicAdd(&g_cursor[d.w], 1)] = s.w;
    }
}

// ---------------------------------------------------------------------------
// K3: aggregation over fp16 h — warp per node, lane = 4 halves (uint2),
// unroll 8 rows; fp32 accumulation.
// ---------------------------------------------------------------------------
__device__ __forceinline__ void h2acc(float4& a, uint2 u) {
    __half2 lo = *(__half2*)&u.x;
    __half2 hi = *(__half2*)&u.y;
    float2 f0 = __half22float2(lo);
    float2 f1 = __half22float2(hi);
    a.x += f0.x; a.y += f0.y; a.z += f1.x; a.w += f1.y;
}

__global__ void __launch_bounds__(256)
agg_kernel() {
    int lane = threadIdx.x & 31;
    int gw = blockIdx.x * 8 + (threadIdx.x >> 5);
    int nw = gridDim.x * 8;
    const uint2* h2 = (const uint2*)g_hhalf;   // 32 uint2 per row
    for (int row = gw; row < NN; row += nw) {
        int beg = __ldg(&g_off[row]);
        int deg = __ldg(&g_off[row + 1]) - beg;
        float4 a0 = make_float4(0.f, 0.f, 0.f, 0.f);
        float4 a1 = a0, a2 = a0, a3 = a0;
        int j = 0;
        for (; j + 8 <= deg; j += 8) {
            int s0 = __ldg(&g_sorted[beg + j]);
            int s1 = __ldg(&g_sorted[beg + j + 1]);
            int s2 = __ldg(&g_sorted[beg + j + 2]);
            int s3 = __ldg(&g_sorted[beg + j + 3]);
            int s4 = __ldg(&g_sorted[beg + j + 4]);
            int s5 = __ldg(&g_sorted[beg + j + 5]);
            int s6 = __ldg(&g_sorted[beg + j + 6]);
            int s7 = __ldg(&g_sorted[beg + j + 7]);
            uint2 v0 = __ldg(&h2[(size_t)s0 * 32 + lane]);
            uint2 v1 = __ldg(&h2[(size_t)s1 * 32 + lane]);
            uint2 v2 = __ldg(&h2[(size_t)s2 * 32 + lane]);
            uint2 v3 = __ldg(&h2[(size_t)s3 * 32 + lane]);
            uint2 v4 = __ldg(&h2[(size_t)s4 * 32 + lane]);
            uint2 v5 = __ldg(&h2[(size_t)s5 * 32 + lane]);
            uint2 v6 = __ldg(&h2[(size_t)s6 * 32 + lane]);
            uint2 v7 = __ldg(&h2[(size_t)s7 * 32 + lane]);
            h2acc(a0, v0); h2acc(a1, v1); h2acc(a2, v2); h2acc(a3, v3);
            h2acc(a0, v4); h2acc(a1, v5); h2acc(a2, v6); h2acc(a3, v7);
        }
        for (; j < deg; j++) {
            int s = __ldg(&g_sorted[beg + j]);
            h2acc(a0, __ldg(&h2[(size_t)s * 32 + lane]));
        }
        float inv = 1.0f / fmaxf((float)deg, 1.0f);
        float4 r;
        r.x = (a0.x + a1.x + a2.x + a3.x) * inv;
        r.y = (a0.y + a1.y + a2.y + a3.y) * inv;
        r.z = (a0.z + a1.z + a2.z + a3.z) * inv;
        r.w = (a0.w + a1.w + a2.w + a3.w) * inv;
        ((float4*)(g_neigh + (size_t)row * DD))[lane] = r;
    }
}

// ---------------------------------------------------------------------------
// K4: fp16 tensor-core dual GEMM (concat K=256, m16n8k16, fp32 accumulate):
//   rst = relu([h | neigh] @ [Ws; Wn] + b), fused BN column stats.
// A [64][264] halves row-major; B transposed [n=128][k=264] halves.
// Fragment loads are single 32-bit LDS, conflict-free (bank = 4*gid+tig).
// 101 KB smem -> 2 CTAs/SM (load/compute overlap across CTAs).
// ---------------------------------------------------------------------------
__global__ void __launch_bounds__(256, 2)
dual_gemm_fp16(const float* __restrict__ Wself,
               const float* __restrict__ Wneigh,
               const float* __restrict__ bias) {
    extern __shared__ __half sm16[];
    __half* sA = sm16;              // 64 x AK
    __half* sB = sm16 + A_HALVES;   // 128 x AK

    const int t    = threadIdx.x;
    const int lane = t & 31;
    const int wid  = t >> 5;
    const int gid  = lane >> 2;   // 0..7
    const int tig  = lane & 3;    // 0..3
    const int wm   = wid & 1;     // warp row 0..1
    const int wn   = wid >> 1;    // warp col 0..3
    const int row_base = blockIdx.x * RBM;

    // --- A load: cols 0..127 straight from g_hhalf (uint2 = 4 halves) ---
    {
        const uint2* hh = (const uint2*)g_hhalf;
        for (int f = t; f < 64 * 32; f += 256) {
            int r  = f >> 5;
            int c4 = f & 31;          // 4-half unit
            int row = row_base + r;
            uint2 u = make_uint2(0u, 0u);
            if (row < NN) u = __ldg(&hh[(size_t)row * 32 + c4]);
            *(uint2*)&sA[r * AK + c4 * 4] = u;
        }
        // cols 128..255 from g_neigh (fp32 -> fp16)
        for (int f = t; f < 64 * 32; f += 256) {
            int r  = f >> 5;
            int c4 = f & 31;
            int row = row_base + r;
            uint2 u = make_uint2(0u, 0u);
            if (row < NN) {
                float4 v = ((const float4*)(g_neigh + (size_t)row * DD))[c4];
                __half2 lo = __floats2half2_rn(v.x, v.y);
                __half2 hi = __floats2half2_rn(v.z, v.w);
                u.x = *(uint32_t*)&lo;
                u.y = *(uint32_t*)&hi;
            }
            *(uint2*)&sA[r * AK + 128 + c4 * 4] = u;
        }
    }
    // --- B load+transpose: sB[n][k] = W[k][n]; k<128 Ws, else Wn ---
    for (int f = t; f < 256 * 128; f += 256) {
        int k = f >> 7;            // same k across the warp
        int n = f & 127;           // n = consecutive within warp (coalesced)
        const float* W = (k < 128) ? Wself : Wneigh;
        float v = __ldg(&W[(k & 127) * DD + n]);
        sB[n * AK + k] = __float2half_rn(v);
    }
    __syncthreads();

    float acc[2][4][4];
    #pragma unroll
    for (int mi = 0; mi < 2; mi++)
        #pragma unroll
        for (int ni = 0; ni < 4; ni++)
            #pragma unroll
            for (int c = 0; c < 4; c++) acc[mi][ni][c] = 0.f;

    #pragma unroll 4
    for (int ks = 0; ks < 16; ks++) {
        int kb = ks * 16;
        uint32_t a[2][4], b[4][2];
        #pragma unroll
        for (int mi = 0; mi < 2; mi++) {
            int r0 = wm * 32 + mi * 16 + gid;
            a[mi][0] = *(const uint32_t*)&sA[r0 * AK + kb + 2 * tig];
            a[mi][1] = *(const uint32_t*)&sA[(r0 + 8) * AK + kb + 2 * tig];
            a[mi][2] = *(const uint32_t*)&sA[r0 * AK + kb + 2 * tig + 8];
            a[mi][3] = *(const uint32_t*)&sA[(r0 + 8) * AK + kb + 2 * tig + 8];
        }
        #pragma unroll
        for (int ni = 0; ni < 4; ni++) {
            int n0 = wn * 32 + ni * 8 + gid;
            b[ni][0] = *(const uint32_t*)&sB[n0 * AK + kb + 2 * tig];
            b[ni][1] = *(const uint32_t*)&sB[n0 * AK + kb + 2 * tig + 8];
        }
        #pragma unroll
        for (int mi = 0; mi < 2; mi++)
            #pragma unroll
            for (int ni = 0; ni < 4; ni++) {
                asm volatile(
                    "mma.sync.aligned.m16n8k16.row.col.f32.f16.f16.f32 "
                    "{%0,%1,%2,%3}, {%4,%5,%6,%7}, {%8,%9}, {%0,%1,%2,%3};"
                    : "+f"(acc[mi][ni][0]), "+f"(acc[mi][ni][1]),
                      "+f"(acc[mi][ni][2]), "+f"(acc[mi][ni][3])
                    : "r"(a[mi][0]), "r"(a[mi][1]), "r"(a[mi][2]), "r"(a[mi][3]),
                      "r"(b[ni][0]), "r"(b[ni][1]));
            }
    }

    // --- epilogue: bias, relu, store, per-thread BN stats ---
    float2 bv[4];
    #pragma unroll
    for (int ni = 0; ni < 4; ni++) {
        int col = wn * 32 + ni * 8 + 2 * tig;
        bv[ni] = *(const float2*)&bias[col];
    }

    float lsum[4][2], lsq[4][2];
    #pragma unroll
    for (int ni = 0; ni < 4; ni++) {
        lsum[ni][0] = lsum[ni][1] = 0.f;
        lsq[ni][0] = lsq[ni][1] = 0.f;
    }

    #pragma unroll
    for (int mi = 0; mi < 2; mi++) {
        #pragma unroll
        for (int half = 0; half < 2; half++) {
            int row = row_base + wm * 32 + mi * 16 + half * 8 + gid;
            if (row < NN) {
                #pragma unroll
                for (int ni = 0; ni < 4; ni++) {
                    int col = wn * 32 + ni * 8 + 2 * tig;
                    float v0 = fmaxf(acc[mi][ni][half * 2]     + bv[ni].x, 0.f);
                    float v1 = fmaxf(acc[mi][ni][half * 2 + 1] + bv[ni].y, 0.f);
                    lsum[ni][0] += v0; lsq[ni][0] += v0 * v0;
                    lsum[ni][1] += v1; lsq[ni][1] += v1 * v1;
                    *(float2*)&g_rst[(size_t)row * DD + col] = make_float2(v0, v1);
                }
            }
        }
    }

    // warp-reduce stats over gid lanes, then global atomics
    #pragma unroll
    for (int ni = 0; ni < 4; ni++)
        #pragma unroll
        for (int s = 0; s < 2; s++) {
            #pragma unroll
            for (int off = 4; off <= 16; off <<= 1) {
                lsum[ni][s] += __shfl_xor_sync(0xffffffffu, lsum[ni][s], off);
                lsq[ni][s]  += __shfl_xor_sync(0xffffffffu, lsq[ni][s],  off);
            }
        }
    if (gid == 0) {
        #pragma unroll
        for (int ni = 0; ni < 4; ni++) {
            int col = wn * 32 + ni * 8 + 2 * tig;
            atomicAdd(&g_colsum[col],       lsum[ni][0]);
            atomicAdd(&g_colsum[col + 1],   lsum[ni][1]);
            atomicAdd(&g_colsumsq[col],     lsq[ni][0]);
            atomicAdd(&g_colsumsq[col + 1], lsq[ni][1]);
        }
    }
}

// ---------------------------------------------------------------------------
// K5: finalize BN coefficients
// ---------------------------------------------------------------------------
__global__ void finalize_kernel(const float* __restrict__ gamma,
                                const float* __restrict__ beta) {
    int c = threadIdx.x;
    const float invN = 1.0f / (float)NN;
    float mean = g_colsum[c] * invN;
    float var  = g_colsumsq[c] * invN - mean * mean;
    float a = gamma[c] * rsqrtf(var + EPS);
    g_coefA[c] = a;
    g_coefB[c] = beta[c] - mean * a;
}

// ---------------------------------------------------------------------------
// K6: out = h + rst * A[c] + B[c]; tail re-zeroes counters/stats.
// ---------------------------------------------------------------------------
__global__ void output_kernel(const float* __restrict__ h,
                              float* __restrict__ out) {
    int i = blockIdx.x * blockDim.x + threadIdx.x;
    int stride = gridDim.x * blockDim.x;
    const int nf4 = NN * DD / 4;
    for (int f = i; f < nf4; f += stride) {
        int cg = f & 31;
        float4 a  = ((const float4*)g_coefA)[cg];
        float4 bb = ((const float4*)g_coefB)[cg];
        float4 hv = ((const float4*)h)[f];
        float4 rv = ((const float4*)g_rst)[f];
        float4 o;
        o.x = hv.x + rv.x * a.x + bb.x;
        o.y = hv.y + rv.y * a.y + bb.y;
        o.z = hv.z + rv.z * a.z + bb.z;
        o.w = hv.w + rv.w * a.w + bb.w;
        ((float4*)out)[f] = o;
    }
    for (int f = i; f < NN; f += stride) g_cnt[f] = 0;
    if (i < DD) { g_colsum[i] = 0.f; g_colsumsq[i] = 0.f; }
}

// ---------------------------------------------------------------------------
extern "C" void kernel_launch(void* const* d_in, const int* in_sizes, int n_in,
                              void* d_out, int out_size) {
    const float* h      = (const float*)d_in[0];
    const int*   src    = (const int*)d_in[1];
    const int*   dst    = (const int*)d_in[2];
    const float* Wself  = (const float*)d_in[3];
    const float* Wneigh = (const float*)d_in[4];
    const float* bias   = (const float*)d_in[5];
    const float* gamma  = (const float*)d_in[6];
    const float* beta   = (const float*)d_in[7];
    float*       out    = (float*)d_out;

    hist_convert_kernel<<<2048, 256>>>(dst, h);   // 0
    scan_kernel<<<1, SCAN_T>>>();                 // 1
    fill_kernel<<<2048, 256>>>(src, dst);         // 2
    agg_kernel<<<2048, 256>>>();                  // 3 (profiled slot)

    cudaFuncSetAttribute(dual_gemm_fp16,
                         cudaFuncAttributeMaxDynamicSharedMemorySize,
                         GEMM_SMEM);
    dual_gemm_fp16<<<GEMM_BLOCKS, 256, GEMM_SMEM>>>(Wself, Wneigh, bias);

    finalize_kernel<<<1, DD>>>(gamma, beta);
    output_kernel<<<2048, 256>>>(h, out);
}

// round 12
// speedup vs baseline: 1.8737x; 1.3804x over previous
#include <cuda_runtime.h>
#include <cuda_fp16.h>
#include <cstdint>

#define NN 100000
#define EE 3200000
#define DD 128
#define EPS 1e-5f

#define RBM 64                               // rows per GEMM block
#define GEMM_BLOCKS ((NN + RBM - 1) / RBM)   // 1563

// fp16 GEMM smem: A [64][AK] halves, B(transposed) [128][BK] halves
#define AK 264                               // A stride: perfect LDS banks
#define BK 266                               // B stride: odd word-stride -> conflict-free STS
#define A_HALVES (64 * AK)                   // 16896
#define B_HALVES (128 * BK)                  // 34048
#define GEMM_SMEM ((A_HALVES + B_HALVES) * 2)  // 101888 B -> 2 CTAs/SM

// Scratch (allocation-free rule: __device__ globals; zero-initialized at load,
// re-zeroed at the tail of output_kernel / end of scan each execution).
__device__ __half g_hhalf[NN * DD];    // fp16 copy of h
__device__ __half g_neigh16[NN * DD];  // fp16 mean-aggregated neighbor features
__device__ __half g_rst16[NN * DD];    // fp16 post-relu activations
__device__ int   g_cnt[NN];            // degree histogram (0 on entry)
__device__ int   g_off[NN + 1];        // CSR exclusive offsets (+ total)
__device__ int   g_cursor[NN];         // fill cursors
__device__ int   g_sorted[EE];         // src sorted by dst
__device__ int   g_done;               // last-block counter (0 on entry)
__device__ float g_colsum[DD];         // 0 on entry
__device__ float g_colsumsq[DD];       // 0 on entry
__device__ float g_coefA[DD];
__device__ float g_coefB[DD];

// ---------------------------------------------------------------------------
// K0: fused: fp16 conversion of h + degree histogram (RED) + (last block)
// coalesced exclusive scan of g_cnt -> g_off / g_cursor.
// ---------------------------------------------------------------------------
#define HIST_BLOCKS 512
#define HIST_T 1024
#define SCAN_TILE (HIST_T * 8)    // 8192 ints per tile

__global__ void __launch_bounds__(HIST_T)
hist_convert_scan(const int* __restrict__ dst, const float* __restrict__ h) {
    int t = threadIdx.x;
    int i = blockIdx.x * HIST_T + t;
    int stride = gridDim.x * HIST_T;

    // --- fp16 conversion: float4 -> 4 halves (uint2) ---
    const float4* h4 = (const float4*)h;
    uint2* o = (uint2*)g_hhalf;
    const int nf4 = NN * DD / 4;
    for (int f = i; f < nf4; f += stride) {
        float4 v = h4[f];
        __half2 lo = __floats2half2_rn(v.x, v.y);
        __half2 hi = __floats2half2_rn(v.z, v.w);
        uint2 u;
        u.x = *(uint32_t*)&lo;
        u.y = *(uint32_t*)&hi;
        o[f] = u;
    }

    // --- histogram (RED, fire-and-forget) ---
    const int4* d4 = (const int4*)dst;
    const int n4 = EE / 4;
    for (int e = i; e < n4; e += stride) {
        int4 d = __ldg(&d4[e]);
        atomicAdd(&g_cnt[d.x], 1);
        atomicAdd(&g_cnt[d.y], 1);
        atomicAdd(&g_cnt[d.z], 1);
        atomicAdd(&g_cnt[d.w], 1);
    }

    // --- last-block detection ---
    __shared__ int is_last;
    __shared__ int warp_sums[32];
    __shared__ int s_base, s_running;
    __syncthreads();
    __threadfence();
    if (t == 0) {
        int old = atomicAdd(&g_done, 1);
        is_last = (old == (int)gridDim.x - 1);
    }
    __syncthreads();
    if (!is_last) return;
    __threadfence();   // acquire: see all g_cnt updates

    // --- tiled exclusive scan, 8 ints per thread per tile ---
    int lane = t & 31;
    int w    = t >> 5;
    if (t == 0) s_running = 0;
    __syncthreads();

    for (int base = 0; base < NN; base += SCAN_TILE) {
        int i0 = base + t * 8;
        int v[8];
        if (i0 + 7 < NN) {
            int4 a = *(const int4*)(g_cnt + i0);
            int4 b = *(const int4*)(g_cnt + i0 + 4);
            v[0]=a.x; v[1]=a.y; v[2]=a.z; v[3]=a.w;
            v[4]=b.x; v[5]=b.y; v[6]=b.z; v[7]=b.w;
        } else {
            #pragma unroll
            for (int j = 0; j < 8; j++)
                v[j] = (i0 + j < NN) ? g_cnt[i0 + j] : 0;
        }
        int s = 0;
        int p[8];
        #pragma unroll
        for (int j = 0; j < 8; j++) { p[j] = s; s += v[j]; }

        // warp-inclusive scan of thread totals
        int x = s;
        #pragma unroll
        for (int off = 1; off < 32; off <<= 1) {
            int y = __shfl_up_sync(0xffffffffu, x, off);
            if (lane >= off) x += y;
        }
        if (lane == 31) warp_sums[w] = x;
        __syncthreads();
        if (t == 0) {
            int run = 0;
            #pragma unroll
            for (int k = 0; k < 32; k++) {
                int tmp = warp_sums[k];
                warp_sums[k] = run;
                run += tmp;
            }
            s_base = s_running;
            s_running += run;
        }
        __syncthreads();

        int texc = s_base + warp_sums[w] + (x - s);
        if (i0 + 7 < NN) {
            int4 oa = make_int4(texc + p[0], texc + p[1], texc + p[2], texc + p[3]);
            int4 ob = make_int4(texc + p[4], texc + p[5], texc + p[6], texc + p[7]);
            *(int4*)(g_off + i0)        = oa;
            *(int4*)(g_off + i0 + 4)    = ob;
            *(int4*)(g_cursor + i0)     = oa;
            *(int4*)(g_cursor + i0 + 4) = ob;
        } else {
            #pragma unroll
            for (int j = 0; j < 8; j++)
                if (i0 + j < NN) {
                    g_off[i0 + j]    = texc + p[j];
                    g_cursor[i0 + j] = texc + p[j];
                }
        }
        __syncthreads();   // protect warp_sums/s_base for next tile
    }
    if (t == 0) {
        g_off[NN] = s_running;
        g_done = 0;        // reset for next replay
    }
}

// ---------------------------------------------------------------------------
// K1: CSR fill — counting sort of src by dst (atomic cursors)
// ---------------------------------------------------------------------------
__global__ void fill_kernel(const int* __restrict__ src,
                            const int* __restrict__ dst) {
    int i = blockIdx.x * blockDim.x + threadIdx.x;
    int stride = gridDim.x * blockDim.x;
    const int4* s4 = (const int4*)src;
    const int4* d4 = (const int4*)dst;
    const int n4 = EE / 4;
    for (int e = i; e < n4; e += stride) {
        int4 d = __ldg(&d4[e]);
        int4 s = __ldg(&s4[e]);
        g_sorted[atomicAdd(&g_cursor[d.x], 1)] = s.x;
        g_sorted[atomicAdd(&g_cursor[d.y], 1)] = s.y;
        g_sorted[atomicAdd(&g_cursor[d.z], 1)] = s.z;
        g_sorted[atomicAdd(&g_cursor[d.w], 1)] = s.w;
    }
}

// ---------------------------------------------------------------------------
// K2: aggregation over fp16 h — warp per node, lane = 4 halves (uint2),
// unroll 8 rows; fp32 accumulation; fp16 output.
// ---------------------------------------------------------------------------
__device__ __forceinline__ void h2acc(float4& a, uint2 u) {
    __half2 lo = *(__half2*)&u.x;
    __half2 hi = *(__half2*)&u.y;
    float2 f0 = __half22float2(lo);
    float2 f1 = __half22float2(hi);
    a.x += f0.x; a.y += f0.y; a.z += f1.x; a.w += f1.y;
}

__global__ void __launch_bounds__(256)
agg_kernel() {
    int lane = threadIdx.x & 31;
    int gw = blockIdx.x * 8 + (threadIdx.x >> 5);
    int nw = gridDim.x * 8;
    const uint2* h2 = (const uint2*)g_hhalf;   // 32 uint2 per row
    for (int row = gw; row < NN; row += nw) {
        int beg = __ldg(&g_off[row]);
        int deg = __ldg(&g_off[row + 1]) - beg;
        float4 a0 = make_float4(0.f, 0.f, 0.f, 0.f);
        float4 a1 = a0, a2 = a0, a3 = a0;
        int j = 0;
        for (; j + 8 <= deg; j += 8) {
            int s0 = __ldg(&g_sorted[beg + j]);
            int s1 = __ldg(&g_sorted[beg + j + 1]);
            int s2 = __ldg(&g_sorted[beg + j + 2]);
            int s3 = __ldg(&g_sorted[beg + j + 3]);
            int s4 = __ldg(&g_sorted[beg + j + 4]);
            int s5 = __ldg(&g_sorted[beg + j + 5]);
            int s6 = __ldg(&g_sorted[beg + j + 6]);
            int s7 = __ldg(&g_sorted[beg + j + 7]);
            uint2 v0 = __ldg(&h2[(size_t)s0 * 32 + lane]);
            uint2 v1 = __ldg(&h2[(size_t)s1 * 32 + lane]);
            uint2 v2 = __ldg(&h2[(size_t)s2 * 32 + lane]);
            uint2 v3 = __ldg(&h2[(size_t)s3 * 32 + lane]);
            uint2 v4 = __ldg(&h2[(size_t)s4 * 32 + lane]);
            uint2 v5 = __ldg(&h2[(size_t)s5 * 32 + lane]);
            uint2 v6 = __ldg(&h2[(size_t)s6 * 32 + lane]);
            uint2 v7 = __ldg(&h2[(size_t)s7 * 32 + lane]);
            h2acc(a0, v0); h2acc(a1, v1); h2acc(a2, v2); h2acc(a3, v3);
            h2acc(a0, v4); h2acc(a1, v5); h2acc(a2, v6); h2acc(a3, v7);
        }
        for (; j < deg; j++) {
            int s = __ldg(&g_sorted[beg + j]);
            h2acc(a0, __ldg(&h2[(size_t)s * 32 + lane]));
        }
        float inv = 1.0f / fmaxf((float)deg, 1.0f);
        __half2 lo = __floats2half2_rn((a0.x + a1.x + a2.x + a3.x) * inv,
                                       (a0.y + a1.y + a2.y + a3.y) * inv);
        __half2 hi = __floats2half2_rn((a0.z + a1.z + a2.z + a3.z) * inv,
                                       (a0.w + a1.w + a2.w + a3.w) * inv);
        uint2 u;
        u.x = *(uint32_t*)&lo;
        u.y = *(uint32_t*)&hi;
        ((uint2*)(g_neigh16 + (size_t)row * DD))[lane] = u;
    }
}

// ---------------------------------------------------------------------------
// K3 (PROFILED SLOT): fp16 tensor-core dual GEMM (concat K=256, m16n8k16):
//   rst = relu([h | neigh] @ [Ws; Wn] + b), fused BN column stats.
// A [64][AK] halves (all-fp16 sources); B transposed [n=128][BK] halves,
// BK=266 -> conflict-free transpose STS. 2 CTAs/SM.
// ---------------------------------------------------------------------------
__global__ void __launch_bounds__(256, 2)
dual_gemm_fp16(const float* __restrict__ Wself,
               const float* __restrict__ Wneigh,
               const float* __restrict__ bias) {
    extern __shared__ __half sm16[];
    __half* sA = sm16;              // 64 x AK
    __half* sB = sm16 + A_HALVES;   // 128 x BK

    const int t    = threadIdx.x;
    const int lane = t & 31;
    const int wid  = t >> 5;
    const int gid  = lane >> 2;   // 0..7
    const int tig  = lane & 3;    // 0..3
    const int wm   = wid & 1;     // warp row 0..1
    const int wn   = wid >> 1;    // warp col 0..3
    const int row_base = blockIdx.x * RBM;

    // --- A load: 64 rows x 64 uint2-units (256 halves = [h16 | neigh16]) ---
    {
        const uint2* hh = (const uint2*)g_hhalf;
        const uint2* nn = (const uint2*)g_neigh16;
        for (int f = t; f < 64 * 64; f += 256) {
            int r  = f >> 6;
            int c4 = f & 63;
            int row = row_base + r;
            uint2 u = make_uint2(0u, 0u);
            if (row < NN) {
                u = (c4 < 32) ? __ldg(&hh[(size_t)row * 32 + c4])
                              : __ldg(&nn[(size_t)row * 32 + (c4 - 32)]);
            }
            *(uint2*)&sA[r * AK + c4 * 4] = u;
        }
    }
    // --- B load+transpose: sB[n][k] = W[k][n]; k<128 Ws, else Wn ---
    for (int f = t; f < 256 * 128; f += 256) {
        int k = f >> 7;
        int n = f & 127;
        const float* W = (k < 128) ? Wself : Wneigh;
        float v = __ldg(&W[(k & 127) * DD + n]);
        sB[n * BK + k] = __float2half_rn(v);
    }
    __syncthreads();

    float acc[2][4][4];
    #pragma unroll
    for (int mi = 0; mi < 2; mi++)
        #pragma unroll
        for (int ni = 0; ni < 4; ni++)
            #pragma unroll
            for (int c = 0; c < 4; c++) acc[mi][ni][c] = 0.f;

    #pragma unroll 4
    for (int ks = 0; ks < 16; ks++) {
        int kb = ks * 16;
        uint32_t a[2][4], b[4][2];
        #pragma unroll
        for (int mi = 0; mi < 2; mi++) {
            int r0 = wm * 32 + mi * 16 + gid;
            a[mi][0] = *(const uint32_t*)&sA[r0 * AK + kb + 2 * tig];
            a[mi][1] = *(const uint32_t*)&sA[(r0 + 8) * AK + kb + 2 * tig];
            a[mi][2] = *(const uint32_t*)&sA[r0 * AK + kb + 2 * tig + 8];
            a[mi][3] = *(const uint32_t*)&sA[(r0 + 8) * AK + kb + 2 * tig + 8];
        }
        #pragma unroll
        for (int ni = 0; ni < 4; ni++) {
            int n0 = wn * 32 + ni * 8 + gid;
            b[ni][0] = *(const uint32_t*)&sB[n0 * BK + kb + 2 * tig];
            b[ni][1] = *(const uint32_t*)&sB[n0 * BK + kb + 2 * tig + 8];
        }
        #pragma unroll
        for (int mi = 0; mi < 2; mi++)
            #pragma unroll
            for (int ni = 0; ni < 4; ni++) {
                asm volatile(
                    "mma.sync.aligned.m16n8k16.row.col.f32.f16.f16.f32 "
                    "{%0,%1,%2,%3}, {%4,%5,%6,%7}, {%8,%9}, {%0,%1,%2,%3};"
                    : "+f"(acc[mi][ni][0]), "+f"(acc[mi][ni][1]),
                      "+f"(acc[mi][ni][2]), "+f"(acc[mi][ni][3])
                    : "r"(a[mi][0]), "r"(a[mi][1]), "r"(a[mi][2]), "r"(a[mi][3]),
                      "r"(b[ni][0]), "r"(b[ni][1]));
            }
    }

    // --- epilogue: bias, relu, fp16 store, per-thread BN stats ---
    float2 bv[4];
    #pragma unroll
    for (int ni = 0; ni < 4; ni++) {
        int col = wn * 32 + ni * 8 + 2 * tig;
        bv[ni] = *(const float2*)&bias[col];
    }

    float lsum[4][2], lsq[4][2];
    #pragma unroll
    for (int ni = 0; ni < 4; ni++) {
        lsum[ni][0] = lsum[ni][1] = 0.f;
        lsq[ni][0] = lsq[ni][1] = 0.f;
    }

    #pragma unroll
    for (int mi = 0; mi < 2; mi++) {
        #pragma unroll
        for (int half = 0; half < 2; half++) {
            int row = row_base + wm * 32 + mi * 16 + half * 8 + gid;
            if (row < NN) {
                #pragma unroll
                for (int ni = 0; ni < 4; ni++) {
                    int col = wn * 32 + ni * 8 + 2 * tig;
                    float v0 = fmaxf(acc[mi][ni][half * 2]     + bv[ni].x, 0.f);
                    float v1 = fmaxf(acc[mi][ni][half * 2 + 1] + bv[ni].y, 0.f);
                    lsum[ni][0] += v0; lsq[ni][0] += v0 * v0;
                    lsum[ni][1] += v1; lsq[ni][1] += v1 * v1;
                    __half2 hv = __floats2half2_rn(v0, v1);
                    *(uint32_t*)&g_rst16[(size_t)row * DD + col] = *(uint32_t*)&hv;
                }
            }
        }
    }

    #pragma unroll
    for (int ni = 0; ni < 4; ni++)
        #pragma unroll
        for (int s = 0; s < 2; s++) {
            #pragma unroll
            for (int off = 4; off <= 16; off <<= 1) {
                lsum[ni][s] += __shfl_xor_sync(0xffffffffu, lsum[ni][s], off);
                lsq[ni][s]  += __shfl_xor_sync(0xffffffffu, lsq[ni][s],  off);
            }
        }
    if (gid == 0) {
        #pragma unroll
        for (int ni = 0; ni < 4; ni++) {
            int col = wn * 32 + ni * 8 + 2 * tig;
            atomicAdd(&g_colsum[col],       lsum[ni][0]);
            atomicAdd(&g_colsum[col + 1],   lsum[ni][1]);
            atomicAdd(&g_colsumsq[col],     lsq[ni][0]);
            atomicAdd(&g_colsumsq[col + 1], lsq[ni][1]);
        }
    }
}

// ---------------------------------------------------------------------------
// K4: finalize BN coefficients
// ---------------------------------------------------------------------------
__global__ void finalize_kernel(const float* __restrict__ gamma,
                                const float* __restrict__ beta) {
    int c = threadIdx.x;
    const float invN = 1.0f / (float)NN;
    float mean = g_colsum[c] * invN;
    float var  = g_colsumsq[c] * invN - mean * mean;
    float a = gamma[c] * rsqrtf(var + EPS);
    g_coefA[c] = a;
    g_coefB[c] = beta[c] - mean * a;
}

// ---------------------------------------------------------------------------
// K5: out = h + rst16 * A[c] + B[c]; tail re-zeroes counters/stats.
// ---------------------------------------------------------------------------
__global__ void output_kernel(const float* __restrict__ h,
                              float* __restrict__ out) {
    int i = blockIdx.x * blockDim.x + threadIdx.x;
    int stride = gridDim.x * blockDim.x;
    const int nf4 = NN * DD / 4;
    const uint2* r2 = (const uint2*)g_rst16;
    for (int f = i; f < nf4; f += stride) {
        int cg = f & 31;
        float4 a  = ((const float4*)g_coefA)[cg];
        float4 bb = ((const float4*)g_coefB)[cg];
        float4 hv = ((const float4*)h)[f];
        uint2 u = r2[f];
        float2 r0 = __half22float2(*(__half2*)&u.x);
        float2 r1 = __half22float2(*(__half2*)&u.y);
        float4 o;
        o.x = hv.x + r0.x * a.x + bb.x;
        o.y = hv.y + r0.y * a.y + bb.y;
        o.z = hv.z + r1.x * a.z + bb.z;
        o.w = hv.w + r1.y * a.w + bb.w;
        ((float4*)out)[f] = o;
    }
    for (int f = i; f < NN; f += stride) g_cnt[f] = 0;
    if (i < DD) { g_colsum[i] = 0.f; g_colsumsq[i] = 0.f; }
}

// ---------------------------------------------------------------------------
extern "C" void kernel_launch(void* const* d_in, const int* in_sizes, int n_in,
                              void* d_out, int out_size) {
    const float* h      = (const float*)d_in[0];
    const int*   src    = (const int*)d_in[1];
    const int*   dst    = (const int*)d_in[2];
    const float* Wself  = (const float*)d_in[3];
    const float* Wneigh = (const float*)d_in[4];
    const float* bias   = (const float*)d_in[5];
    const float* gamma  = (const float*)d_in[6];
    const float* beta   = (const float*)d_in[7];
    float*       out    = (float*)d_out;

    hist_convert_scan<<<HIST_BLOCKS, HIST_T>>>(dst, h);   // 0
    fill_kernel<<<2048, 256>>>(src, dst);                 // 1
    agg_kernel<<<2048, 256>>>();                          // 2

    cudaFuncSetAttribute(dual_gemm_fp16,
                         cudaFuncAttributeMaxDynamicSharedMemorySize,
                         GEMM_SMEM);
    dual_gemm_fp16<<<GEMM_BLOCKS, 256, GEMM_SMEM>>>(Wself, Wneigh, bias);  // 3 <- profiled

    finalize_kernel<<<1, DD>>>(gamma, beta);              // 4
    output_kernel<<<2048, 256>>>(h, out);                 // 5
}

// round 13
// speedup vs baseline: 2.1448x; 1.1447x over previous
#include <cuda_runtime.h>
#include <cuda_fp16.h>
#include <cstdint>

#define NN 100000
#define EE 3200000
#define DD 128
#define EPS 1e-5f

#define RBM 64                               // rows per GEMM block
#define GEMM_BLOCKS ((NN + RBM - 1) / RBM)   // 1563

// fp16 GEMM smem: A [64][AK] halves, B(transposed) [128][BK] halves
// 264 halves = 528 B stride; 528 mod 128 = 16 -> ldmatrix phases hit 8
// distinct 16B segments (conflict-free).
#define AK 264
#define BK 264
#define A_HALVES (64 * AK)                   // 16896
#define B_HALVES (128 * BK)                  // 33792
#define GEMM_SMEM ((A_HALVES + B_HALVES) * 2)  // 101376 B -> 2 CTAs/SM

// Scratch (allocation-free rule: __device__ globals; zero-initialized at load,
// re-zeroed at the tail of output_kernel / end of scan each execution).
__device__ __half g_hhalf[NN * DD];    // fp16 copy of h
__device__ __half g_neigh16[NN * DD];  // fp16 mean-aggregated neighbor features
__device__ __half g_rst16[NN * DD];    // fp16 post-relu activations
__device__ __half g_w16t[128 * 256];   // W transposed+concat: [n][k], k<128 Ws else Wn
__device__ int   g_cnt[NN];            // degree histogram (0 on entry)
__device__ int   g_off[NN + 1];        // CSR exclusive offsets (+ total)
__device__ int   g_cursor[NN];         // fill cursors
__device__ int   g_sorted[EE];         // src sorted by dst
__device__ int   g_done;               // last-block counter (0 on entry)
__device__ float g_colsum[DD];         // 0 on entry
__device__ float g_colsumsq[DD];       // 0 on entry
__device__ float g_coefA[DD];
__device__ float g_coefB[DD];

// ---------------------------------------------------------------------------
// K0: fused: fp16 conversion of h + W transpose to fp16 + degree histogram
// (RED) + (last block) coalesced exclusive scan of g_cnt -> g_off / g_cursor.
// ---------------------------------------------------------------------------
#define HIST_BLOCKS 512
#define HIST_T 1024
#define SCAN_TILE (HIST_T * 8)    // 8192 ints per tile

__global__ void __launch_bounds__(HIST_T)
hist_convert_scan(const int* __restrict__ dst, const float* __restrict__ h,
                  const float* __restrict__ Wself,
                  const float* __restrict__ Wneigh) {
    int t = threadIdx.x;
    int i = blockIdx.x * HIST_T + t;
    int stride = gridDim.x * HIST_T;

    // --- fp16 conversion: float4 -> 4 halves (uint2) ---
    const float4* h4 = (const float4*)h;
    uint2* o = (uint2*)g_hhalf;
    const int nf4 = NN * DD / 4;
    for (int f = i; f < nf4; f += stride) {
        float4 v = h4[f];
        __half2 lo = __floats2half2_rn(v.x, v.y);
        __half2 hi = __floats2half2_rn(v.z, v.w);
        uint2 u;
        u.x = *(uint32_t*)&lo;
        u.y = *(uint32_t*)&hi;
        o[f] = u;
    }

    // --- W transpose: g_w16t[n*256 + k] = fp16(W[k][n]) ---
    for (int f = i; f < 256 * 128; f += stride) {
        int k = f >> 7;
        int n = f & 127;
        const float* W = (k < 128) ? Wself : Wneigh;
        g_w16t[n * 256 + k] = __float2half_rn(__ldg(&W[(k & 127) * DD + n]));
    }

    // --- histogram (RED, fire-and-forget) ---
    const int4* d4 = (const int4*)dst;
    const int n4 = EE / 4;
    for (int e = i; e < n4; e += stride) {
        int4 d = __ldg(&d4[e]);
        atomicAdd(&g_cnt[d.x], 1);
        atomicAdd(&g_cnt[d.y], 1);
        atomicAdd(&g_cnt[d.z], 1);
        atomicAdd(&g_cnt[d.w], 1);
    }

    // --- last-block detection ---
    __shared__ int is_last;
    __shared__ int warp_sums[32];
    __shared__ int s_base, s_running;
    __syncthreads();
    __threadfence();
    if (t == 0) {
        int old = atomicAdd(&g_done, 1);
        is_last = (old == (int)gridDim.x - 1);
    }
    __syncthreads();
    if (!is_last) return;
    __threadfence();   // acquire: see all g_cnt updates

    // --- tiled exclusive scan, 8 ints per thread per tile ---
    int lane = t & 31;
    int w    = t >> 5;
    if (t == 0) s_running = 0;
    __syncthreads();

    for (int base = 0; base < NN; base += SCAN_TILE) {
        int i0 = base + t * 8;
        int v[8];
        if (i0 + 7 < NN) {
            int4 a = *(const int4*)(g_cnt + i0);
            int4 b = *(const int4*)(g_cnt + i0 + 4);
            v[0]=a.x; v[1]=a.y; v[2]=a.z; v[3]=a.w;
            v[4]=b.x; v[5]=b.y; v[6]=b.z; v[7]=b.w;
        } else {
            #pragma unroll
            for (int j = 0; j < 8; j++)
                v[j] = (i0 + j < NN) ? g_cnt[i0 + j] : 0;
        }
        int s = 0;
        int p[8];
        #pragma unroll
        for (int j = 0; j < 8; j++) { p[j] = s; s += v[j]; }

        int x = s;
        #pragma unroll
        for (int off = 1; off < 32; off <<= 1) {
            int y = __shfl_up_sync(0xffffffffu, x, off);
            if (lane >= off) x += y;
        }
        if (lane == 31) warp_sums[w] = x;
        __syncthreads();
        if (t == 0) {
            int run = 0;
            #pragma unroll
            for (int k = 0; k < 32; k++) {
                int tmp = warp_sums[k];
                warp_sums[k] = run;
                run += tmp;
            }
            s_base = s_running;
            s_running += run;
        }
        __syncthreads();

        int texc = s_base + warp_sums[w] + (x - s);
        if (i0 + 7 < NN) {
            int4 oa = make_int4(texc + p[0], texc + p[1], texc + p[2], texc + p[3]);
            int4 ob = make_int4(texc + p[4], texc + p[5], texc + p[6], texc + p[7]);
            *(int4*)(g_off + i0)        = oa;
            *(int4*)(g_off + i0 + 4)    = ob;
            *(int4*)(g_cursor + i0)     = oa;
            *(int4*)(g_cursor + i0 + 4) = ob;
        } else {
            #pragma unroll
            for (int j = 0; j < 8; j++)
                if (i0 + j < NN) {
                    g_off[i0 + j]    = texc + p[j];
                    g_cursor[i0 + j] = texc + p[j];
                }
        }
        __syncthreads();
    }
    if (t == 0) {
        g_off[NN] = s_running;
        g_done = 0;        // reset for next replay
    }
}

// ---------------------------------------------------------------------------
// K1: CSR fill — counting sort of src by dst (atomic cursors)
// ---------------------------------------------------------------------------
__global__ void fill_kernel(const int* __restrict__ src,
                            const int* __restrict__ dst) {
    int i = blockIdx.x * blockDim.x + threadIdx.x;
    int stride = gridDim.x * blockDim.x;
    const int4* s4 = (const int4*)src;
    const int4* d4 = (const int4*)dst;
    const int n4 = EE / 4;
    for (int e = i; e < n4; e += stride) {
        int4 d = __ldg(&d4[e]);
        int4 s = __ldg(&s4[e]);
        g_sorted[atomicAdd(&g_cursor[d.x], 1)] = s.x;
        g_sorted[atomicAdd(&g_cursor[d.y], 1)] = s.y;
        g_sorted[atomicAdd(&g_cursor[d.z], 1)] = s.z;
        g_sorted[atomicAdd(&g_cursor[d.w], 1)] = s.w;
    }
}

// ---------------------------------------------------------------------------
// K2: aggregation over fp16 h — warp per node, lane = 4 halves (uint2),
// unroll 8 rows; fp32 accumulation; fp16 output.
// ---------------------------------------------------------------------------
__device__ __forceinline__ void h2acc(float4& a, uint2 u) {
    __half2 lo = *(__half2*)&u.x;
    __half2 hi = *(__half2*)&u.y;
    float2 f0 = __half22float2(lo);
    float2 f1 = __half22float2(hi);
    a.x += f0.x; a.y += f0.y; a.z += f1.x; a.w += f1.y;
}

__global__ void __launch_bounds__(256)
agg_kernel() {
    int lane = threadIdx.x & 31;
    int gw = blockIdx.x * 8 + (threadIdx.x >> 5);
    int nw = gridDim.x * 8;
    const uint2* h2 = (const uint2*)g_hhalf;   // 32 uint2 per row
    for (int row = gw; row < NN; row += nw) {
        int beg = __ldg(&g_off[row]);
        int deg = __ldg(&g_off[row + 1]) - beg;
        float4 a0 = make_float4(0.f, 0.f, 0.f, 0.f);
        float4 a1 = a0, a2 = a0, a3 = a0;
        int j = 0;
        for (; j + 8 <= deg; j += 8) {
            int s0 = __ldg(&g_sorted[beg + j]);
            int s1 = __ldg(&g_sorted[beg + j + 1]);
            int s2 = __ldg(&g_sorted[beg + j + 2]);
            int s3 = __ldg(&g_sorted[beg + j + 3]);
            int s4 = __ldg(&g_sorted[beg + j + 4]);
            int s5 = __ldg(&g_sorted[beg + j + 5]);
            int s6 = __ldg(&g_sorted[beg + j + 6]);
            int s7 = __ldg(&g_sorted[beg + j + 7]);
            uint2 v0 = __ldg(&h2[(size_t)s0 * 32 + lane]);
            uint2 v1 = __ldg(&h2[(size_t)s1 * 32 + lane]);
            uint2 v2 = __ldg(&h2[(size_t)s2 * 32 + lane]);
            uint2 v3 = __ldg(&h2[(size_t)s3 * 32 + lane]);
            uint2 v4 = __ldg(&h2[(size_t)s4 * 32 + lane]);
            uint2 v5 = __ldg(&h2[(size_t)s5 * 32 + lane]);
            uint2 v6 = __ldg(&h2[(size_t)s6 * 32 + lane]);
            uint2 v7 = __ldg(&h2[(size_t)s7 * 32 + lane]);
            h2acc(a0, v0); h2acc(a1, v1); h2acc(a2, v2); h2acc(a3, v3);
            h2acc(a0, v4); h2acc(a1, v5); h2acc(a2, v6); h2acc(a3, v7);
        }
        for (; j < deg; j++) {
            int s = __ldg(&g_sorted[beg + j]);
            h2acc(a0, __ldg(&h2[(size_t)s * 32 + lane]));
        }
        float inv = 1.0f / fmaxf((float)deg, 1.0f);
        __half2 lo = __floats2half2_rn((a0.x + a1.x + a2.x + a3.x) * inv,
                                       (a0.y + a1.y + a2.y + a3.y) * inv);
        __half2 hi = __floats2half2_rn((a0.z + a1.z + a2.z + a3.z) * inv,
                                       (a0.w + a1.w + a2.w + a3.w) * inv);
        uint2 u;
        u.x = *(uint32_t*)&lo;
        u.y = *(uint32_t*)&hi;
        ((uint2*)(g_neigh16 + (size_t)row * DD))[lane] = u;
    }
}

// ---------------------------------------------------------------------------
// K3 (PROFILED SLOT): fp16 tensor-core dual GEMM (concat K=256, m16n8k16):
//   rst = relu([h | neigh] @ [Ws; Wn] + b), fused BN column stats.
// B pre-transposed in gmem (g_w16t) -> staging is a pure coalesced copy.
// Fragments via ldmatrix.m8n8.x4 (conflict-free, stride 528B).
// ---------------------------------------------------------------------------
__global__ void __launch_bounds__(256, 2)
dual_gemm_fp16(const float* __restrict__ bias) {
    extern __shared__ __half sm16[];
    __half* sA = sm16;              // 64 x AK
    __half* sB = sm16 + A_HALVES;   // 128 x BK

    const int t    = threadIdx.x;
    const int lane = t & 31;
    const int wid  = t >> 5;
    const int gid  = lane >> 2;   // 0..7
    const int tig  = lane & 3;    // 0..3
    const int wm   = wid & 1;     // warp row 0..1
    const int wn   = wid >> 1;    // warp col 0..3
    const int row_base = blockIdx.x * RBM;

    // --- A load: 64 rows x 64 uint2-units (256 halves = [h16 | neigh16]) ---
    {
        const uint2* hh = (const uint2*)g_hhalf;
        const uint2* nn = (const uint2*)g_neigh16;
        for (int f = t; f < 64 * 64; f += 256) {
            int r  = f >> 6;
            int c4 = f & 63;
            int row = row_base + r;
            uint2 u = make_uint2(0u, 0u);
            if (row < NN) {
                u = (c4 < 32) ? __ldg(&hh[(size_t)row * 32 + c4])
                              : __ldg(&nn[(size_t)row * 32 + (c4 - 32)]);
            }
            *(uint2*)&sA[r * AK + c4 * 4] = u;
        }
    }
    // --- B copy: g_w16t[n][k] -> sB[n][k] (coalesced, conflict-free) ---
    {
        const uint2* wt = (const uint2*)g_w16t;   // 64 uint2 per row
        for (int f = t; f < 128 * 64; f += 256) {
            int n = f >> 6;
            int u = f & 63;
            *(uint2*)&sB[n * BK + u * 4] = __ldg(&wt[n * 64 + u]);
        }
    }
    __syncthreads();

    // --- ldmatrix per-thread base addresses ---
    int arow  = wm * 32 + ((lane >> 3) & 1) * 8 + (lane & 7);
    int akoff = (lane >> 4) * 8;
    uint32_t aAddr0 = (uint32_t)__cvta_generic_to_shared(&sA[arow * AK + akoff]);
    uint32_t aAddr1 = (uint32_t)__cvta_generic_to_shared(&sA[(arow + 16) * AK + akoff]);
    int brow = wn * 32 + (lane >> 3) * 8 + (lane & 7);
    uint32_t bAddr0 = (uint32_t)__cvta_generic_to_shared(&sB[brow * BK]);
    uint32_t bAddr1 = (uint32_t)__cvta_generic_to_shared(&sB[brow * BK + 8]);

    float acc[2][4][4];
    #pragma unroll
    for (int mi = 0; mi < 2; mi++)
        #pragma unroll
        for (int ni = 0; ni < 4; ni++)
            #pragma unroll
            for (int c = 0; c < 4; c++) acc[mi][ni][c] = 0.f;

    #pragma unroll 4
    for (int ks = 0; ks < 16; ks++) {
        uint32_t koff = ks * 32;   // 16 halves = 32 bytes per kstep
        uint32_t a[2][4], b0[4], b1[4];
        asm volatile("ldmatrix.sync.aligned.m8n8.x4.shared.b16 {%0,%1,%2,%3}, [%4];"
            : "=r"(a[0][0]), "=r"(a[0][1]), "=r"(a[0][2]), "=r"(a[0][3])
            : "r"(aAddr0 + koff));
        asm volatile("ldmatrix.sync.aligned.m8n8.x4.shared.b16 {%0,%1,%2,%3}, [%4];"
            : "=r"(a[1][0]), "=r"(a[1][1]), "=r"(a[1][2]), "=r"(a[1][3])
            : "r"(aAddr1 + koff));
        asm volatile("ldmatrix.sync.aligned.m8n8.x4.shared.b16 {%0,%1,%2,%3}, [%4];"
            : "=r"(b0[0]), "=r"(b0[1]), "=r"(b0[2]), "=r"(b0[3])
            : "r"(bAddr0 + koff));
        asm volatile("ldmatrix.sync.aligned.m8n8.x4.shared.b16 {%0,%1,%2,%3}, [%4];"
            : "=r"(b1[0]), "=r"(b1[1]), "=r"(b1[2]), "=r"(b1[3])
            : "r"(bAddr1 + koff));

        #pragma unroll
        for (int mi = 0; mi < 2; mi++)
            #pragma unroll
            for (int ni = 0; ni < 4; ni++) {
                asm volatile(
                    "mma.sync.aligned.m16n8k16.row.col.f32.f16.f16.f32 "
                    "{%0,%1,%2,%3}, {%4,%5,%6,%7}, {%8,%9}, {%0,%1,%2,%3};"
                    : "+f"(acc[mi][ni][0]), "+f"(acc[mi][ni][1]),
                      "+f"(acc[mi][ni][2]), "+f"(acc[mi][ni][3])
                    : "r"(a[mi][0]), "r"(a[mi][1]), "r"(a[mi][2]), "r"(a[mi][3]),
                      "r"(b0[ni]), "r"(b1[ni]));
            }
    }

    // --- epilogue: bias, relu, fp16 store, per-thread BN stats ---
    float2 bv[4];
    #pragma unroll
    for (int ni = 0; ni < 4; ni++) {
        int col = wn * 32 + ni * 8 + 2 * tig;
        bv[ni] = *(const float2*)&bias[col];
    }

    float lsum[4][2], lsq[4][2];
    #pragma unroll
    for (int ni = 0; ni < 4; ni++) {
        lsum[ni][0] = lsum[ni][1] = 0.f;
        lsq[ni][0] = lsq[ni][1] = 0.f;
    }

    #pragma unroll
    for (int mi = 0; mi < 2; mi++) {
        #pragma unroll
        for (int half = 0; half < 2; half++) {
            int row = row_base + wm * 32 + mi * 16 + half * 8 + gid;
            if (row < NN) {
                #pragma unroll
                for (int ni = 0; ni < 4; ni++) {
                    int col = wn * 32 + ni * 8 + 2 * tig;
                    float v0 = fmaxf(acc[mi][ni][half * 2]     + bv[ni].x, 0.f);
                    float v1 = fmaxf(acc[mi][ni][half * 2 + 1] + bv[ni].y, 0.f);
                    lsum[ni][0] += v0; lsq[ni][0] += v0 * v0;
                    lsum[ni][1] += v1; lsq[ni][1] += v1 * v1;
                    __half2 hv = __floats2half2_rn(v0, v1);
                    *(uint32_t*)&g_rst16[(size_t)row * DD + col] = *(uint32_t*)&hv;
                }
            }
        }
    }

    #pragma unroll
    for (int ni = 0; ni < 4; ni++)
        #pragma unroll
        for (int s = 0; s < 2; s++) {
            #pragma unroll
            for (int off = 4; off <= 16; off <<= 1) {
                lsum[ni][s] += __shfl_xor_sync(0xffffffffu, lsum[ni][s], off);
                lsq[ni][s]  += __shfl_xor_sync(0xffffffffu, lsq[ni][s],  off);
            }
        }
    if (gid == 0) {
        #pragma unroll
        for (int ni = 0; ni < 4; ni++) {
            int col = wn * 32 + ni * 8 + 2 * tig;
            atomicAdd(&g_colsum[col],       lsum[ni][0]);
            atomicAdd(&g_colsum[col + 1],   lsum[ni][1]);
            atomicAdd(&g_colsumsq[col],     lsq[ni][0]);
            atomicAdd(&g_colsumsq[col + 1], lsq[ni][1]);
        }
    }
}

// ---------------------------------------------------------------------------
// K4: finalize BN coefficients
// ---------------------------------------------------------------------------
__global__ void finalize_kernel(const float* __restrict__ gamma,
                                const float* __restrict__ beta) {
    int c = threadIdx.x;
    const float invN = 1.0f / (float)NN;
    float mean = g_colsum[c] * invN;
    float var  = g_colsumsq[c] * invN - mean * mean;
    float a = gamma[c] * rsqrtf(var + EPS);
    g_coefA[c] = a;
    g_coefB[c] = beta[c] - mean * a;
}

// ---------------------------------------------------------------------------
// K5: out = h + rst16 * A[c] + B[c]; tail re-zeroes counters/stats.
// ---------------------------------------------------------------------------
__global__ void output_kernel(const float* __restrict__ h,
                              float* __restrict__ out) {
    int i = blockIdx.x * blockDim.x + threadIdx.x;
    int stride = gridDim.x * blockDim.x;
    const int nf4 = NN * DD / 4;
    const uint2* r2 = (const uint2*)g_rst16;
    for (int f = i; f < nf4; f += stride) {
        int cg = f & 31;
        float4 a  = ((const float4*)g_coefA)[cg];
        float4 bb = ((const float4*)g_coefB)[cg];
        float4 hv = ((const float4*)h)[f];
        uint2 u = r2[f];
        float2 r0 = __half22float2(*(__half2*)&u.x);
        float2 r1 = __half22float2(*(__half2*)&u.y);
        float4 o;
        o.x = hv.x + r0.x * a.x + bb.x;
        o.y = hv.y + r0.y * a.y + bb.y;
        o.z = hv.z + r1.x * a.z + bb.z;
        o.w = hv.w + r1.y * a.w + bb.w;
        ((float4*)out)[f] = o;
    }
    for (int f = i; f < NN; f += stride) g_cnt[f] = 0;
    if (i < DD) { g_colsum[i] = 0.f; g_colsumsq[i] = 0.f; }
}

// ---------------------------------------------------------------------------
extern "C" void kernel_launch(void* const* d_in, const int* in_sizes, int n_in,
                              void* d_out, int out_size) {
    const float* h      = (const float*)d_in[0];
    const int*   src    = (const int*)d_in[1];
    const int*   dst    = (const int*)d_in[2];
    const float* Wself  = (const float*)d_in[3];
    const float* Wneigh = (const float*)d_in[4];
    const float* bias   = (const float*)d_in[5];
    const float* gamma  = (const float*)d_in[6];
    const float* beta   = (const float*)d_in[7];
    float*       out    = (float*)d_out;

    hist_convert_scan<<<HIST_BLOCKS, HIST_T>>>(dst, h, Wself, Wneigh);  // 0
    fill_kernel<<<2048, 256>>>(src, dst);                               // 1
    agg_kernel<<<2048, 256>>>();                                       // 2

    cudaFuncSetAttribute(dual_gemm_fp16,
                         cudaFuncAttributeMaxDynamicSharedMemorySize,
                         GEMM_SMEM);
    dual_gemm_fp16<<<GEMM_BLOCKS, 256, GEMM_SMEM>>>(bias);             // 3 <- profiled

    finalize_kernel<<<1, DD>>>(gamma, beta);                           // 4
    output_kernel<<<2048, 256>>>(h, out);                              // 5
}

// round 15
// speedup vs baseline: 2.3803x; 1.1098x over previous
#include <cuda_runtime.h>
#include <cuda_fp16.h>
#include <cstdint>

#define NN 100000
#define EE 3200000
#define DD 128
#define EPS 1e-5f

#define RBM 64                               // rows per GEMM tile
#define GEMM_TILES ((NN + RBM - 1) / RBM)    // 1563
#define GEMM_CTAS 148                        // persistent, 1 per SM

// fp16 GEMM smem: two A buffers [64][AK] + B [128][BK]
// 264-half stride (528 B); 528 mod 128 = 16 -> ldmatrix conflict-free.
#define AK 264
#define BK 264
#define A_HALVES (64 * AK)                   // 16896 halves = 33792 B
#define B_HALVES (128 * BK)                  // 33792 halves = 67584 B
#define A_BYTES (A_HALVES * 2)
#define GEMM_SMEM ((2 * A_HALVES + B_HALVES) * 2)   // 135168 B -> 1 CTA/SM

// Scratch (allocation-free rule: __device__ globals; zero-initialized at load,
// re-zeroed at the tail of output_kernel / end of scan each execution).
__device__ __half g_hhalf[NN * DD];    // fp16 copy of h
__device__ __half g_neigh16[NN * DD];  // fp16 mean-aggregated neighbor features
__device__ __half g_rst16[NN * DD];    // fp16 post-relu activations
__device__ __half g_w16t[128 * 256];   // W transposed+concat: [n][k]
__device__ int   g_cnt[NN];            // degree histogram (0 on entry)
__device__ int   g_off[NN + 1];        // CSR exclusive offsets (+ total)
__device__ int   g_cursor[NN];         // fill cursors
__device__ int   g_sorted[EE];         // src sorted by dst
__device__ int   g_done;               // last-block counter (0 on entry)
__device__ float g_colsum[DD];         // 0 on entry
__device__ float g_colsumsq[DD];       // 0 on entry
__device__ float g_coefA[DD];
__device__ float g_coefB[DD];

// ---------------------------------------------------------------------------
// K0: fused: fp16 conversion of h + W transpose + histogram (RED) +
// (last block) coalesced exclusive scan of g_cnt -> g_off / g_cursor.
// ---------------------------------------------------------------------------
#define HIST_BLOCKS 512
#define HIST_T 1024
#define SCAN_TILE (HIST_T * 8)

__global__ void __launch_bounds__(HIST_T)
hist_convert_scan(const int* __restrict__ dst, const float* __restrict__ h,
                  const float* __restrict__ Wself,
                  const float* __restrict__ Wneigh) {
    int t = threadIdx.x;
    int i = blockIdx.x * HIST_T + t;
    int stride = gridDim.x * HIST_T;

    const float4* h4 = (const float4*)h;
    uint2* o = (uint2*)g_hhalf;
    const int nf4 = NN * DD / 4;
    for (int f = i; f < nf4; f += stride) {
        float4 v = h4[f];
        __half2 lo = __floats2half2_rn(v.x, v.y);
        __half2 hi = __floats2half2_rn(v.z, v.w);
        uint2 u;
        u.x = *(uint32_t*)&lo;
        u.y = *(uint32_t*)&hi;
        o[f] = u;
    }

    for (int f = i; f < 256 * 128; f += stride) {
        int k = f >> 7;
        int n = f & 127;
        const float* W = (k < 128) ? Wself : Wneigh;
        g_w16t[n * 256 + k] = __float2half_rn(__ldg(&W[(k & 127) * DD + n]));
    }

    const int4* d4 = (const int4*)dst;
    const int n4 = EE / 4;
    for (int e = i; e < n4; e += stride) {
        int4 d = __ldg(&d4[e]);
        atomicAdd(&g_cnt[d.x], 1);
        atomicAdd(&g_cnt[d.y], 1);
        atomicAdd(&g_cnt[d.z], 1);
        atomicAdd(&g_cnt[d.w], 1);
    }

    __shared__ int is_last;
    __shared__ int warp_sums[32];
    __shared__ int s_base, s_running;
    __syncthreads();
    __threadfence();
    if (t == 0) {
        int old = atomicAdd(&g_done, 1);
        is_last = (old == (int)gridDim.x - 1);
    }
    __syncthreads();
    if (!is_last) return;
    __threadfence();

    int lane = t & 31;
    int w    = t >> 5;
    if (t == 0) s_running = 0;
    __syncthreads();

    for (int base = 0; base < NN; base += SCAN_TILE) {
        int i0 = base + t * 8;
        int v[8];
        if (i0 + 7 < NN) {
            int4 a = *(const int4*)(g_cnt + i0);
            int4 b = *(const int4*)(g_cnt + i0 + 4);
            v[0]=a.x; v[1]=a.y; v[2]=a.z; v[3]=a.w;
            v[4]=b.x; v[5]=b.y; v[6]=b.z; v[7]=b.w;
        } else {
            #pragma unroll
            for (int j = 0; j < 8; j++)
                v[j] = (i0 + j < NN) ? g_cnt[i0 + j] : 0;
        }
        int s = 0;
        int p[8];
        #pragma unroll
        for (int j = 0; j < 8; j++) { p[j] = s; s += v[j]; }

        int x = s;
        #pragma unroll
        for (int off = 1; off < 32; off <<= 1) {
            int y = __shfl_up_sync(0xffffffffu, x, off);
            if (lane >= off) x += y;
        }
        if (lane == 31) warp_sums[w] = x;
        __syncthreads();
        if (t == 0) {
            int run = 0;
            #pragma unroll
            for (int k = 0; k < 32; k++) {
                int tmp = warp_sums[k];
                warp_sums[k] = run;
                run += tmp;
            }
            s_base = s_running;
            s_running += run;
        }
        __syncthreads();

        int texc = s_base + warp_sums[w] + (x - s);
        if (i0 + 7 < NN) {
            int4 oa = make_int4(texc + p[0], texc + p[1], texc + p[2], texc + p[3]);
            int4 ob = make_int4(texc + p[4], texc + p[5], texc + p[6], texc + p[7]);
            *(int4*)(g_off + i0)        = oa;
            *(int4*)(g_off + i0 + 4)    = ob;
            *(int4*)(g_cursor + i0)     = oa;
            *(int4*)(g_cursor + i0 + 4) = ob;
        } else {
            #pragma unroll
            for (int j = 0; j < 8; j++)
                if (i0 + j < NN) {
                    g_off[i0 + j]    = texc + p[j];
                    g_cursor[i0 + j] = texc + p[j];
                }
        }
        __syncthreads();
    }
    if (t == 0) {
        g_off[NN] = s_running;
        g_done = 0;
    }
}

// ---------------------------------------------------------------------------
// K1: CSR fill — counting sort; 8 edges (two int4) per iter for deeper MLP.
// ---------------------------------------------------------------------------
__global__ void fill_kernel(const int* __restrict__ src,
                            const int* __restrict__ dst) {
    int i = blockIdx.x * blockDim.x + threadIdx.x;
    int stride = gridDim.x * blockDim.x;
    const int4* s4 = (const int4*)src;
    const int4* d4 = (const int4*)dst;
    const int n8 = EE / 8;
    for (int e = i; e < n8; e += stride) {
        int4 d0 = __ldg(&d4[2 * e]);
        int4 d1 = __ldg(&d4[2 * e + 1]);
        int4 s0 = __ldg(&s4[2 * e]);
        int4 s1 = __ldg(&s4[2 * e + 1]);
        g_sorted[atomicAdd(&g_cursor[d0.x], 1)] = s0.x;
        g_sorted[atomicAdd(&g_cursor[d0.y], 1)] = s0.y;
        g_sorted[atomicAdd(&g_cursor[d0.z], 1)] = s0.z;
        g_sorted[atomicAdd(&g_cursor[d0.w], 1)] = s0.w;
        g_sorted[atomicAdd(&g_cursor[d1.x], 1)] = s1.x;
        g_sorted[atomicAdd(&g_cursor[d1.y], 1)] = s1.y;
        g_sorted[atomicAdd(&g_cursor[d1.z], 1)] = s1.z;
        g_sorted[atomicAdd(&g_cursor[d1.w], 1)] = s1.w;
    }
}

// ---------------------------------------------------------------------------
// K2: aggregation over fp16 h — warp per node, fp32 accumulation, fp16 out.
// ---------------------------------------------------------------------------
__device__ __forceinline__ void h2acc(float4& a, uint2 u) {
    __half2 lo = *(__half2*)&u.x;
    __half2 hi = *(__half2*)&u.y;
    float2 f0 = __half22float2(lo);
    float2 f1 = __half22float2(hi);
    a.x += f0.x; a.y += f0.y; a.z += f1.x; a.w += f1.y;
}

__global__ void __launch_bounds__(256)
agg_kernel() {
    int lane = threadIdx.x & 31;
    int gw = blockIdx.x * 8 + (threadIdx.x >> 5);
    int nw = gridDim.x * 8;
    const uint2* h2 = (const uint2*)g_hhalf;
    for (int row = gw; row < NN; row += nw) {
        int beg = __ldg(&g_off[row]);
        int deg = __ldg(&g_off[row + 1]) - beg;
        float4 a0 = make_float4(0.f, 0.f, 0.f, 0.f);
        float4 a1 = a0, a2 = a0, a3 = a0;
        int j = 0;
        for (; j + 8 <= deg; j += 8) {
            int s0 = __ldg(&g_sorted[beg + j]);
            int s1 = __ldg(&g_sorted[beg + j + 1]);
            int s2 = __ldg(&g_sorted[beg + j + 2]);
            int s3 = __ldg(&g_sorted[beg + j + 3]);
            int s4 = __ldg(&g_sorted[beg + j + 4]);
            int s5 = __ldg(&g_sorted[beg + j + 5]);
            int s6 = __ldg(&g_sorted[beg + j + 6]);
            int s7 = __ldg(&g_sorted[beg + j + 7]);
            uint2 v0 = __ldg(&h2[(size_t)s0 * 32 + lane]);
            uint2 v1 = __ldg(&h2[(size_t)s1 * 32 + lane]);
            uint2 v2 = __ldg(&h2[(size_t)s2 * 32 + lane]);
            uint2 v3 = __ldg(&h2[(size_t)s3 * 32 + lane]);
            uint2 v4 = __ldg(&h2[(size_t)s4 * 32 + lane]);
            uint2 v5 = __ldg(&h2[(size_t)s5 * 32 + lane]);
            uint2 v6 = __ldg(&h2[(size_t)s6 * 32 + lane]);
            uint2 v7 = __ldg(&h2[(size_t)s7 * 32 + lane]);
            h2acc(a0, v0); h2acc(a1, v1); h2acc(a2, v2); h2acc(a3, v3);
            h2acc(a0, v4); h2acc(a1, v5); h2acc(a2, v6); h2acc(a3, v7);
        }
        for (; j < deg; j++) {
            int s = __ldg(&g_sorted[beg + j]);
            h2acc(a0, __ldg(&h2[(size_t)s * 32 + lane]));
        }
        float inv = 1.0f / fmaxf((float)deg, 1.0f);
        __half2 lo = __floats2half2_rn((a0.x + a1.x + a2.x + a3.x) * inv,
                                       (a0.y + a1.y + a2.y + a3.y) * inv);
        __half2 hi = __floats2half2_rn((a0.z + a1.z + a2.z + a3.z) * inv,
                                       (a0.w + a1.w + a2.w + a3.w) * inv);
        uint2 u;
        u.x = *(uint32_t*)&lo;
        u.y = *(uint32_t*)&hi;
        ((uint2*)(g_neigh16 + (size_t)row * DD))[lane] = u;
    }
}

// ---------------------------------------------------------------------------
// K3 (PROFILED SLOT): persistent double-buffered fp16 tensor GEMM.
// 148 CTAs, each processes tiles cta, cta+148, ... with cp.async prefetch of
// the next A tile overlapping the current tile's mma. B staged once.
// ---------------------------------------------------------------------------
__device__ __forceinline__ void prefetch_a(int tile, int t, uint32_t sa_base) {
    int row_base = tile * RBM;
    const char* hh = (const char*)g_hhalf;
    const char* nn = (const char*)g_neigh16;
    #pragma unroll
    for (int it = 0; it < 8; it++) {
        int f = t + it * 256;         // 0..2047
        int r = f >> 5;
        int chunk = f & 31;           // 16B unit within 512B row
        int row = row_base + r;
        int rowc = row < NN ? row : 0;
        const char* src = (chunk < 16)
            ? hh + (size_t)rowc * 256 + chunk * 16
            : nn + (size_t)rowc * 256 + (chunk - 16) * 16;
        uint32_t dst = sa_base + r * (AK * 2) + chunk * 16;
        int sz = (row < NN) ? 16 : 0;
        asm volatile("cp.async.cg.shared.global [%0], [%1], 16, %2;"
                     :: "r"(dst), "l"(src), "r"(sz));
    }
}

__global__ void __launch_bounds__(256, 1)
dual_gemm_fp16(const float* __restrict__ bias) {
    extern __shared__ __half sm16[];
    __half* sA = sm16;                       // 2 x (64 x AK)
    __half* sB = sm16 + 2 * A_HALVES;        // 128 x BK

    const int t    = threadIdx.x;
    const int lane = t & 31;
    const int wid  = t >> 5;
    const int gid  = lane >> 2;
    const int tig  = lane & 3;
    const int wm   = wid & 1;
    const int wn   = wid >> 1;

    // --- B staging (once): coalesced copy of pre-transposed W ---
    {
        const uint2* wt = (const uint2*)g_w16t;
        for (int f = t; f < 128 * 64; f += 256) {
            int n = f >> 6;
            int u = f & 63;
            *(uint2*)&sB[n * BK + u * 4] = __ldg(&wt[n * 64 + u]);
        }
    }

    // --- ldmatrix base addresses (buffer 0); buffer1 = +A_BYTES ---
    int arow  = wm * 32 + ((lane >> 3) & 1) * 8 + (lane & 7);
    int akoff = (lane >> 4) * 8;
    uint32_t aAddr0 = (uint32_t)__cvta_generic_to_shared(&sA[arow * AK + akoff]);
    uint32_t aAddr1 = (uint32_t)__cvta_generic_to_shared(&sA[(arow + 16) * AK + akoff]);
    int brow = wn * 32 + (lane >> 3) * 8 + (lane & 7);
    uint32_t bAddr0 = (uint32_t)__cvta_generic_to_shared(&sB[brow * BK]);
    uint32_t bAddr1 = (uint32_t)__cvta_generic_to_shared(&sB[brow * BK + 8]);
    uint32_t sa_shared = (uint32_t)__cvta_generic_to_shared(sA);

    float2 bv[4];
    #pragma unroll
    for (int ni = 0; ni < 4; ni++) {
        int col = wn * 32 + ni * 8 + 2 * tig;
        bv[ni] = *(const float2*)&bias[col];
    }
    float lsum[4][2], lsq[4][2];
    #pragma unroll
    for (int ni = 0; ni < 4; ni++) {
        lsum[ni][0] = lsum[ni][1] = 0.f;
        lsq[ni][0] = lsq[ni][1] = 0.f;
    }

    // --- persistent tile loop with double-buffered prefetch ---
    int p = 0;
    int tile0 = blockIdx.x;
    if (tile0 < GEMM_TILES) prefetch_a(tile0, t, sa_shared);
    asm volatile("cp.async.commit_group;");

    for (int tile = tile0; tile < GEMM_TILES; tile += GEMM_CTAS) {
        int next = tile + GEMM_CTAS;
        if (next < GEMM_TILES)
            prefetch_a(next, t, sa_shared + (p ^ 1) * A_BYTES);
        asm volatile("cp.async.commit_group;");
        asm volatile("cp.async.wait_group 1;");
        __syncthreads();

        uint32_t abase = (uint32_t)(p * A_BYTES);
        float acc[2][4][4];
        #pragma unroll
        for (int mi = 0; mi < 2; mi++)
            #pragma unroll
            for (int ni = 0; ni < 4; ni++)
                #pragma unroll
                for (int c = 0; c < 4; c++) acc[mi][ni][c] = 0.f;

        #pragma unroll 4
        for (int ks = 0; ks < 16; ks++) {
            uint32_t koff = ks * 32;
            uint32_t a[2][4], b0[4], b1[4];
            asm volatile("ldmatrix.sync.aligned.m8n8.x4.shared.b16 {%0,%1,%2,%3}, [%4];"
                : "=r"(a[0][0]), "=r"(a[0][1]), "=r"(a[0][2]), "=r"(a[0][3])
                : "r"(aAddr0 + abase + koff));
            asm volatile("ldmatrix.sync.aligned.m8n8.x4.shared.b16 {%0,%1,%2,%3}, [%4];"
                : "=r"(a[1][0]), "=r"(a[1][1]), "=r"(a[1][2]), "=r"(a[1][3])
                : "r"(aAddr1 + abase + koff));
            asm volatile("ldmatrix.sync.aligned.m8n8.x4.shared.b16 {%0,%1,%2,%3}, [%4];"
                : "=r"(b0[0]), "=r"(b0[1]), "=r"(b0[2]), "=r"(b0[3])
                : "r"(bAddr0 + koff));
            asm volatile("ldmatrix.sync.aligned.m8n8.x4.shared.b16 {%0,%1,%2,%3}, [%4];"
                : "=r"(b1[0]), "=r"(b1[1]), "=r"(b1[2]), "=r"(b1[3])
                : "r"(bAddr1 + koff));

            #pragma unroll
            for (int mi = 0; mi < 2; mi++)
                #pragma unroll
                for (int ni = 0; ni < 4; ni++) {
                    asm volatile(
                        "mma.sync.aligned.m16n8k16.row.col.f32.f16.f16.f32 "
                        "{%0,%1,%2,%3}, {%4,%5,%6,%7}, {%8,%9}, {%0,%1,%2,%3};"
                        : "+f"(acc[mi][ni][0]), "+f"(acc[mi][ni][1]),
                          "+f"(acc[mi][ni][2]), "+f"(acc[mi][ni][3])
                        : "r"(a[mi][0]), "r"(a[mi][1]), "r"(a[mi][2]), "r"(a[mi][3]),
                          "r"(b0[ni]), "r"(b1[ni]));
                }
        }

        // epilogue: bias, relu, fp16 store, stats accumulate
        int row_base = tile * RBM;
        #pragma unroll
        for (int mi = 0; mi < 2; mi++) {
            #pragma unroll
            for (int half = 0; half < 2; half++) {
                int row = row_base + wm * 32 + mi * 16 + half * 8 + gid;
                if (row < NN) {
                    #pragma unroll
                    for (int ni = 0; ni < 4; ni++) {
                        int col = wn * 32 + ni * 8 + 2 * tig;
                        float v0 = fmaxf(acc[mi][ni][half * 2]     + bv[ni].x, 0.f);
                        float v1 = fmaxf(acc[mi][ni][half * 2 + 1] + bv[ni].y, 0.f);
                        lsum[ni][0] += v0; lsq[ni][0] += v0 * v0;
                        lsum[ni][1] += v1; lsq[ni][1] += v1 * v1;
                        __half2 hv = __floats2half2_rn(v0, v1);
                        *(uint32_t*)&g_rst16[(size_t)row * DD + col] = *(uint32_t*)&hv;
                    }
                }
            }
        }
        __syncthreads();   // compute done before next prefetch overwrites buf p
        p ^= 1;
    }

    // one stats reduction per CTA
    #pragma unroll
    for (int ni = 0; ni < 4; ni++)
        #pragma unroll
        for (int s = 0; s < 2; s++) {
            #pragma unroll
            for (int off = 4; off <= 16; off <<= 1) {
                lsum[ni][s] += __shfl_xor_sync(0xffffffffu, lsum[ni][s], off);
                lsq[ni][s]  += __shfl_xor_sync(0xffffffffu, lsq[ni][s],  off);
            }
        }
    if (gid == 0) {
        #pragma unroll
        for (int ni = 0; ni < 4; ni++) {
            int col = wn * 32 + ni * 8 + 2 * tig;
            atomicAdd(&g_colsum[col],       lsum[ni][0]);
            atomicAdd(&g_colsum[col + 1],   lsum[ni][1]);
            atomicAdd(&g_colsumsq[col],     lsq[ni][0]);
            atomicAdd(&g_colsumsq[col + 1], lsq[ni][1]);
        }
    }
}

// ---------------------------------------------------------------------------
// K4: finalize BN coefficients
// ---------------------------------------------------------------------------
__global__ void finalize_kernel(const float* __restrict__ gamma,
                                const float* __restrict__ beta) {
    int c = threadIdx.x;
    const float invN = 1.0f / (float)NN;
    float mean = g_colsum[c] * invN;
    float var  = g_colsumsq[c] * invN - mean * mean;
    float a = gamma[c] * rsqrtf(var + EPS);
    g_coefA[c] = a;
    g_coefB[c] = beta[c] - mean * a;
}

// ---------------------------------------------------------------------------
// K5: out = h + rst16 * A[c] + B[c]; tail re-zeroes counters/stats.
// ---------------------------------------------------------------------------
__global__ void output_kernel(const float* __restrict__ h,
                              float* __restrict__ out) {
    int i = blockIdx.x * blockDim.x + threadIdx.x;
    int stride = gridDim.x * blockDim.x;
    const int nf4 = NN * DD / 4;
    const uint2* r2 = (const uint2*)g_rst16;
    for (int f = i; f < nf4; f += stride) {
        int cg = f & 31;
        float4 a  = ((const float4*)g_coefA)[cg];
        float4 bb = ((const float4*)g_coefB)[cg];
        float4 hv = ((const float4*)h)[f];
        uint2 u = r2[f];
        float2 r0 = __half22float2(*(__half2*)&u.x);
        float2 r1 = __half22float2(*(__half2*)&u.y);
        float4 o;
        o.x = hv.x + r0.x * a.x + bb.x;
        o.y = hv.y + r0.y * a.y + bb.y;
        o.z = hv.z + r1.x * a.z + bb.z;
        o.w = hv.w + r1.y * a.w + bb.w;
        ((float4*)out)[f] = o;
    }
    for (int f = i; f < NN; f += stride) g_cnt[f] = 0;
    if (i < DD) { g_colsum[i] = 0.f; g_colsumsq[i] = 0.f; }
}

// ---------------------------------------------------------------------------
extern "C" void kernel_launch(void* const* d_in, const int* in_sizes, int n_in,
                              void* d_out, int out_size) {
    const float* h      = (const float*)d_in[0];
    const int*   src    = (const int*)d_in[1];
    const int*   dst    = (const int*)d_in[2];
    const float* Wself  = (const float*)d_in[3];
    const float* Wneigh = (const float*)d_in[4];
    const float* bias   = (const float*)d_in[5];
    const float* gamma  = (const float*)d_in[6];
    const float* beta   = (const float*)d_in[7];
    float*       out    = (float*)d_out;

    hist_convert_scan<<<HIST_BLOCKS, HIST_T>>>(dst, h, Wself, Wneigh);  // 0
    fill_kernel<<<2048, 256>>>(src, dst);                               // 1
    agg_kernel<<<2048, 256>>>();                                       // 2

    cudaFuncSetAttribute(dual_gemm_fp16,
                         cudaFuncAttributeMaxDynamicSharedMemorySize,
                         GEMM_SMEM);
    dual_gemm_fp16<<<GEMM_CTAS, 256, GEMM_SMEM>>>(bias);               // 3 <- profiled

    finalize_kernel<<<1, DD>>>(gamma, beta);                           // 4
    output_kernel<<<2048, 256>>>(h, out);                              // 5
}